// round 1
// baseline (speedup 1.0000x reference)
#include <cuda_runtime.h>
#include <math.h>

#define NN 50000
#define CC 256
#define EE 800000
#define HH 64
#define KK 32
#define LL 2

// ---- scratch (no allocation allowed) ----
__device__ float g_h[NN * HH];     // node state
__device__ float g_m[NN * HH];     // scatter accumulator
__device__ float g_deg[NN];        // weighted degree
__device__ float g_rho[NN];        // sigmoid(rho_raw)

// =====================================================================
// Encoder: h = relu(relu(x @ W1 + b1) @ W2 + b2)
// block = 256 threads = 4 nodes x 64 channels
// =====================================================================
__global__ void k_encoder(const float* __restrict__ x,
                          const float* __restrict__ w1, const float* __restrict__ b1,
                          const float* __restrict__ w2, const float* __restrict__ b2) {
    __shared__ float sx[4][CC];
    __shared__ float sh1[4][HH];
    int tid = threadIdx.x;
    int g = tid >> 6;        // node within block
    int j = tid & 63;        // channel
    int nbase = blockIdx.x * 4;

    for (int idx = tid; idx < 4 * CC; idx += 256) {
        int gg = idx / CC, c = idx % CC;
        sx[gg][c] = x[(size_t)(nbase + gg) * CC + c];
    }
    __syncthreads();

    float acc = b1[j];
#pragma unroll 8
    for (int c = 0; c < CC; c++)
        acc = fmaf(sx[g][c], w1[c * HH + j], acc);
    sh1[g][j] = fmaxf(acc, 0.f);
    __syncthreads();

    float acc2 = b2[j];
#pragma unroll
    for (int i = 0; i < HH; i++)
        acc2 = fmaf(sh1[g][i], w2[i * HH + j], acc2);
    g_h[(size_t)(nbase + g) * HH + j] = fmaxf(acc2, 0.f);
}

// =====================================================================
// rho = sigmoid(rho_raw)
// =====================================================================
__global__ void k_rho(const float* __restrict__ rho_raw) {
    int i = blockIdx.x * blockDim.x + threadIdx.x;
    if (i < NN) g_rho[i] = 1.f / (1.f + __expf(-rho_raw[i]));
}

// =====================================================================
// zero m and deg
// =====================================================================
__global__ void k_zero() {
    int i = blockIdx.x * blockDim.x + threadIdx.x;
    if (i < NN * HH) g_m[i] = 0.f;
    if (i < NN) g_deg[i] = 0.f;
}

// =====================================================================
// Edge kernel: warp per edge.
//   z = relu([h_src | h_dst] @ gate_w1 + gate_b1)   (64 channels, 2/lane)
//   gate = sigmoid(z @ gate_w2 + gate_b2)
//   w = base_w * gate * rho[src]*rho[dst]
//   atomic: m[dst] += w*h_src ; deg[dst] += w
// gate_w1 staged in smem as float2 pairs: sw[i*32+l] = (W1[i][l], W1[i][l+32])
// =====================================================================
__global__ void __launch_bounds__(256) k_edge(
        const int* __restrict__ src, const int* __restrict__ dst,
        const float* __restrict__ basew,
        const float* __restrict__ gw1, const float* __restrict__ gb1,
        const float* __restrict__ gw2, const float* __restrict__ gb2) {
    __shared__ float2 sw[128 * 32];
    __shared__ float2 sb1[32];
    __shared__ float  sw2[64];
    __shared__ float  sb2;
    int tid = threadIdx.x;

    for (int idx = tid; idx < 128 * 32; idx += 256) {
        int i = idx >> 5, l = idx & 31;
        sw[idx] = make_float2(gw1[i * 64 + l], gw1[i * 64 + l + 32]);
    }
    if (tid < 32) sb1[tid] = make_float2(gb1[tid], gb1[tid + 32]);
    if (tid < 64) sw2[tid] = gw2[tid];
    if (tid == 0) sb2 = gb2[0];
    __syncthreads();

    int lane = tid & 31;
    int warp = tid >> 5;
    int stride = gridDim.x * 8;

    for (int e = blockIdx.x * 8 + warp; e < EE; e += stride) {
        int s = src[e], d = dst[e];
        const float* hs = g_h + (size_t)s * HH;
        const float* hd = g_h + (size_t)d * HH;
        float hsx = hs[lane], hsy = hs[lane + 32];
        float hdx = hd[lane], hdy = hd[lane + 32];

        float2 acc = sb1[lane];
#pragma unroll
        for (int i = 0; i < 32; i++) {
            float a = __shfl_sync(0xffffffffu, hsx, i);
            float2 w = sw[i * 32 + lane];
            acc.x = fmaf(a, w.x, acc.x); acc.y = fmaf(a, w.y, acc.y);
        }
#pragma unroll
        for (int i = 0; i < 32; i++) {
            float a = __shfl_sync(0xffffffffu, hsy, i);
            float2 w = sw[(i + 32) * 32 + lane];
            acc.x = fmaf(a, w.x, acc.x); acc.y = fmaf(a, w.y, acc.y);
        }
#pragma unroll
        for (int i = 0; i < 32; i++) {
            float a = __shfl_sync(0xffffffffu, hdx, i);
            float2 w = sw[(i + 64) * 32 + lane];
            acc.x = fmaf(a, w.x, acc.x); acc.y = fmaf(a, w.y, acc.y);
        }
#pragma unroll
        for (int i = 0; i < 32; i++) {
            float a = __shfl_sync(0xffffffffu, hdy, i);
            float2 w = sw[(i + 96) * 32 + lane];
            acc.x = fmaf(a, w.x, acc.x); acc.y = fmaf(a, w.y, acc.y);
        }

        float part = fmaxf(acc.x, 0.f) * sw2[lane] + fmaxf(acc.y, 0.f) * sw2[lane + 32];
#pragma unroll
        for (int off = 16; off; off >>= 1)
            part += __shfl_xor_sync(0xffffffffu, part, off);

        float gate = 1.f / (1.f + __expf(-(part + sb2)));
        float wt = basew[e] * gate * g_rho[s] * g_rho[d];

        atomicAdd(&g_m[(size_t)d * HH + lane],      wt * hsx);
        atomicAdd(&g_m[(size_t)d * HH + lane + 32], wt * hsy);
        if (lane == 0) atomicAdd(&g_deg[d], wt);
    }
}

// =====================================================================
// Node update + LayerNorm. block = 256 = 4 nodes x 64 channels.
//   neigh = m/(deg+eps); u = relu(neigh@W1+b1)@W2+b2
//   h = LN(h + u) * g + b
// =====================================================================
__global__ void k_update(const float* __restrict__ uw1, const float* __restrict__ ub1,
                         const float* __restrict__ uw2, const float* __restrict__ ub2,
                         const float* __restrict__ lng, const float* __restrict__ lnb) {
    __shared__ float sn[4][HH];
    __shared__ float st[4][HH];
    __shared__ float2 red[8];
    int tid = threadIdx.x;
    int g = tid >> 6;
    int j = tid & 63;
    int n = blockIdx.x * 4 + g;

    float deg = g_deg[n];
    float nb = g_m[(size_t)n * HH + j] / (deg + 1e-8f);
    sn[g][j] = nb;
    __syncthreads();

    float a = ub1[j];
#pragma unroll
    for (int i = 0; i < HH; i++)
        a = fmaf(sn[g][i], uw1[i * HH + j], a);
    st[g][j] = fmaxf(a, 0.f);
    __syncthreads();

    float u = ub2[j];
#pragma unroll
    for (int i = 0; i < HH; i++)
        u = fmaf(st[g][i], uw2[i * HH + j], u);

    float pre = g_h[(size_t)n * HH + j] + u;

    float s1 = pre, s2 = pre * pre;
#pragma unroll
    for (int off = 16; off; off >>= 1) {
        s1 += __shfl_xor_sync(0xffffffffu, s1, off);
        s2 += __shfl_xor_sync(0xffffffffu, s2, off);
    }
    int warp = tid >> 5;
    if ((tid & 31) == 0) red[warp] = make_float2(s1, s2);
    __syncthreads();

    float tsum = red[g * 2].x + red[g * 2 + 1].x;
    float tsq  = red[g * 2].y + red[g * 2 + 1].y;
    float mean = tsum * (1.f / HH);
    float var  = tsq * (1.f / HH) - mean * mean;
    float inv  = rsqrtf(var + 1e-5f);
    g_h[(size_t)n * HH + j] = (pre - mean) * inv * lng[j] + lnb[j];
}

// =====================================================================
// Head: U = softplus(h @ toU_w + toU_b). block = 256 = 8 nodes x 32.
// =====================================================================
__global__ void k_head(const float* __restrict__ tw, const float* __restrict__ tb,
                       float* __restrict__ out) {
    __shared__ float sh[8][HH];
    int tid = threadIdx.x;
    int g = tid >> 5;
    int k = tid & 31;
    int nbase = blockIdx.x * 8;

    for (int idx = tid; idx < 8 * HH; idx += 256) {
        int gg = idx >> 6, jj = idx & 63;
        sh[gg][jj] = g_h[(size_t)(nbase + gg) * HH + jj];
    }
    __syncthreads();

    float a = tb[k];
#pragma unroll
    for (int j = 0; j < HH; j++)
        a = fmaf(sh[g][j], tw[j * KK + k], a);
    // softplus(x) = log1p(exp(-|x|)) + max(x,0)
    out[(size_t)(nbase + g) * KK + k] = log1pf(__expf(-fabsf(a))) + fmaxf(a, 0.f);
}

// =====================================================================
extern "C" void kernel_launch(void* const* d_in, const int* in_sizes, int n_in,
                              void* d_out, int out_size) {
    const float* x      = (const float*)d_in[0];
    const int*   src    = (const int*)  d_in[1];
    const int*   dst    = (const int*)  d_in[2];
    const float* basew  = (const float*)d_in[3];
    const float* enc_w1 = (const float*)d_in[4];
    const float* enc_b1 = (const float*)d_in[5];
    const float* enc_w2 = (const float*)d_in[6];
    const float* enc_b2 = (const float*)d_in[7];
    const float* gw1    = (const float*)d_in[8];
    const float* gb1    = (const float*)d_in[9];
    const float* gw2    = (const float*)d_in[10];
    const float* gb2    = (const float*)d_in[11];
    const float* uw1    = (const float*)d_in[12];
    const float* ub1    = (const float*)d_in[13];
    const float* uw2    = (const float*)d_in[14];
    const float* ub2    = (const float*)d_in[15];
    const float* lng    = (const float*)d_in[16];
    const float* lnb    = (const float*)d_in[17];
    const float* rho    = (const float*)d_in[18];
    const float* tw     = (const float*)d_in[19];
    const float* tb     = (const float*)d_in[20];
    float* out = (float*)d_out;

    k_encoder<<<NN / 4, 256>>>(x, enc_w1, enc_b1, enc_w2, enc_b2);
    k_rho<<<(NN + 255) / 256, 256>>>(rho);

    for (int l = 0; l < LL; l++) {
        k_zero<<<(NN * HH + 255) / 256, 256>>>();
        k_edge<<<2048, 256>>>(src, dst, basew, gw1, gb1, gw2, gb2);
        k_update<<<NN / 4, 256>>>(uw1 + l * HH * HH, ub1 + l * HH,
                                  uw2 + l * HH * HH, ub2 + l * HH,
                                  lng + l * HH, lnb + l * HH);
    }

    k_head<<<NN / 8, 256>>>(tw, tb, out);
}

// round 2
// speedup vs baseline: 1.6637x; 1.6637x over previous
#include <cuda_runtime.h>
#include <math.h>

#define NN 50000
#define CC 256
#define EE 800000
#define HH 64
#define KK 32
#define LL 2

// ---- scratch (no allocation allowed) ----
__device__ float g_h[NN * HH];     // node state
__device__ float g_m[NN * HH];     // scatter accumulator (zero-invariant between runs)
__device__ float g_deg[NN];        // weighted degree (zero-invariant between runs)
__device__ float g_rho[NN];        // sigmoid(rho_raw)

// =====================================================================
// Encoder: h = relu(relu(x @ W1 + b1) @ W2 + b2)
// block = 256 threads = 4 nodes x 64 channels
// =====================================================================
__global__ void k_encoder(const float* __restrict__ x,
                          const float* __restrict__ w1, const float* __restrict__ b1,
                          const float* __restrict__ w2, const float* __restrict__ b2) {
    __shared__ float sx[4][CC];
    __shared__ float sh1[4][HH];
    int tid = threadIdx.x;
    int g = tid >> 6;        // node within block
    int j = tid & 63;        // channel
    int nbase = blockIdx.x * 4;

    for (int idx = tid; idx < 4 * CC; idx += 256) {
        int gg = idx / CC, c = idx % CC;
        sx[gg][c] = x[(size_t)(nbase + gg) * CC + c];
    }
    __syncthreads();

    float acc = b1[j];
#pragma unroll 8
    for (int c = 0; c < CC; c++)
        acc = fmaf(sx[g][c], w1[c * HH + j], acc);
    sh1[g][j] = fmaxf(acc, 0.f);
    __syncthreads();

    float acc2 = b2[j];
#pragma unroll
    for (int i = 0; i < HH; i++)
        acc2 = fmaf(sh1[g][i], w2[i * HH + j], acc2);
    g_h[(size_t)(nbase + g) * HH + j] = fmaxf(acc2, 0.f);
}

// =====================================================================
// rho = sigmoid(rho_raw)
// =====================================================================
__global__ void k_rho(const float* __restrict__ rho_raw) {
    int i = blockIdx.x * blockDim.x + threadIdx.x;
    if (i < NN) g_rho[i] = 1.f / (1.f + __expf(-rho_raw[i]));
}

// =====================================================================
// Edge kernel: warp per 4 edges (T=4 batching amortizes W1 smem reads 4x).
//   z = relu([h_src | h_dst] @ gate_w1 + gate_b1)   (64 channels, 2/lane)
//   gate = sigmoid(z @ gate_w2 + gate_b2)
//   w = base_w * gate * rho[src]*rho[dst]
//   atomic: m[dst] += w*h_src ; deg[dst] += w
// gate_w1 staged in smem as float2 pairs: sw[i*32+l] = (W1[i][l], W1[i][l+32])
// =====================================================================
#define TEDGE 4
__global__ void __launch_bounds__(256) k_edge(
        const int* __restrict__ src, const int* __restrict__ dst,
        const float* __restrict__ basew,
        const float* __restrict__ gw1, const float* __restrict__ gb1,
        const float* __restrict__ gw2, const float* __restrict__ gb2) {
    __shared__ float2 sw[128 * 32];
    __shared__ float2 sb1[32];
    __shared__ float  sw2[64];
    __shared__ float  sb2;
    int tid = threadIdx.x;

    for (int idx = tid; idx < 128 * 32; idx += 256) {
        int i = idx >> 5, l = idx & 31;
        sw[idx] = make_float2(gw1[i * 64 + l], gw1[i * 64 + l + 32]);
    }
    if (tid < 32) sb1[tid] = make_float2(gb1[tid], gb1[tid + 32]);
    if (tid < 64) sw2[tid] = gw2[tid];
    if (tid == 0) sb2 = gb2[0];
    __syncthreads();

    int lane = tid & 31;
    int warp = tid >> 5;
    int stride = gridDim.x * 8 * TEDGE;

    // EE divisible by TEDGE -> always full tiles
    for (int e0 = (blockIdx.x * 8 + warp) * TEDGE; e0 < EE; e0 += stride) {
        int sA[TEDGE], dA[TEDGE];
        float hsx[TEDGE], hsy[TEDGE], hdx[TEDGE], hdy[TEDGE];
        float2 acc[TEDGE];
#pragma unroll
        for (int t = 0; t < TEDGE; t++) {
            sA[t] = __ldg(src + e0 + t);
            dA[t] = __ldg(dst + e0 + t);
            const float* hs = g_h + (size_t)sA[t] * HH;
            const float* hd = g_h + (size_t)dA[t] * HH;
            hsx[t] = hs[lane]; hsy[t] = hs[lane + 32];
            hdx[t] = hd[lane]; hdy[t] = hd[lane + 32];
            acc[t] = sb1[lane];
        }

#pragma unroll
        for (int i = 0; i < 32; i++) {
            float2 w = sw[i * 32 + lane];
#pragma unroll
            for (int t = 0; t < TEDGE; t++) {
                float a = __shfl_sync(0xffffffffu, hsx[t], i);
                acc[t].x = fmaf(a, w.x, acc[t].x); acc[t].y = fmaf(a, w.y, acc[t].y);
            }
        }
#pragma unroll
        for (int i = 0; i < 32; i++) {
            float2 w = sw[(i + 32) * 32 + lane];
#pragma unroll
            for (int t = 0; t < TEDGE; t++) {
                float a = __shfl_sync(0xffffffffu, hsy[t], i);
                acc[t].x = fmaf(a, w.x, acc[t].x); acc[t].y = fmaf(a, w.y, acc[t].y);
            }
        }
#pragma unroll
        for (int i = 0; i < 32; i++) {
            float2 w = sw[(i + 64) * 32 + lane];
#pragma unroll
            for (int t = 0; t < TEDGE; t++) {
                float a = __shfl_sync(0xffffffffu, hdx[t], i);
                acc[t].x = fmaf(a, w.x, acc[t].x); acc[t].y = fmaf(a, w.y, acc[t].y);
            }
        }
#pragma unroll
        for (int i = 0; i < 32; i++) {
            float2 w = sw[(i + 96) * 32 + lane];
#pragma unroll
            for (int t = 0; t < TEDGE; t++) {
                float a = __shfl_sync(0xffffffffu, hdy[t], i);
                acc[t].x = fmaf(a, w.x, acc[t].x); acc[t].y = fmaf(a, w.y, acc[t].y);
            }
        }

#pragma unroll
        for (int t = 0; t < TEDGE; t++) {
            float part = fmaxf(acc[t].x, 0.f) * sw2[lane]
                       + fmaxf(acc[t].y, 0.f) * sw2[lane + 32];
#pragma unroll
            for (int off = 16; off; off >>= 1)
                part += __shfl_xor_sync(0xffffffffu, part, off);

            float gate = 1.f / (1.f + __expf(-(part + sb2)));
            float wt = __ldg(basew + e0 + t) * gate * g_rho[sA[t]] * g_rho[dA[t]];

            atomicAdd(&g_m[(size_t)dA[t] * HH + lane],      wt * hsx[t]);
            atomicAdd(&g_m[(size_t)dA[t] * HH + lane + 32], wt * hsy[t]);
            if (lane == 0) atomicAdd(&g_deg[dA[t]], wt);
        }
    }
}

// =====================================================================
// Node update + LayerNorm. block = 256 = 4 nodes x 64 channels.
//   neigh = m/(deg+eps); u = relu(neigh@W1+b1)@W2+b2
//   h = LN(h + u) * g + b
// Also resets g_m/g_deg to zero (so no separate zeroing pass is needed;
// invariant holds across graph replays).
// =====================================================================
__global__ void k_update(const float* __restrict__ uw1, const float* __restrict__ ub1,
                         const float* __restrict__ uw2, const float* __restrict__ ub2,
                         const float* __restrict__ lng, const float* __restrict__ lnb) {
    __shared__ float sn[4][HH];
    __shared__ float st[4][HH];
    __shared__ float2 red[8];
    int tid = threadIdx.x;
    int g = tid >> 6;
    int j = tid & 63;
    int n = blockIdx.x * 4 + g;

    float deg = g_deg[n];
    float nb = g_m[(size_t)n * HH + j] / (deg + 1e-8f);
    sn[g][j] = nb;
    __syncthreads();

    // reset accumulators for next layer / next replay
    g_m[(size_t)n * HH + j] = 0.f;
    if (j == 0) g_deg[n] = 0.f;

    float a = ub1[j];
#pragma unroll
    for (int i = 0; i < HH; i++)
        a = fmaf(sn[g][i], uw1[i * HH + j], a);
    st[g][j] = fmaxf(a, 0.f);
    __syncthreads();

    float u = ub2[j];
#pragma unroll
    for (int i = 0; i < HH; i++)
        u = fmaf(st[g][i], uw2[i * HH + j], u);

    float pre = g_h[(size_t)n * HH + j] + u;

    float s1 = pre, s2 = pre * pre;
#pragma unroll
    for (int off = 16; off; off >>= 1) {
        s1 += __shfl_xor_sync(0xffffffffu, s1, off);
        s2 += __shfl_xor_sync(0xffffffffu, s2, off);
    }
    int warp = tid >> 5;
    if ((tid & 31) == 0) red[warp] = make_float2(s1, s2);
    __syncthreads();

    float tsum = red[g * 2].x + red[g * 2 + 1].x;
    float tsq  = red[g * 2].y + red[g * 2 + 1].y;
    float mean = tsum * (1.f / HH);
    float var  = tsq * (1.f / HH) - mean * mean;
    float inv  = rsqrtf(var + 1e-5f);
    g_h[(size_t)n * HH + j] = (pre - mean) * inv * lng[j] + lnb[j];
}

// =====================================================================
// Head: U = softplus(h @ toU_w + toU_b). block = 256 = 8 nodes x 32.
// =====================================================================
__global__ void k_head(const float* __restrict__ tw, const float* __restrict__ tb,
                       float* __restrict__ out) {
    __shared__ float sh[8][HH];
    int tid = threadIdx.x;
    int g = tid >> 5;
    int k = tid & 31;
    int nbase = blockIdx.x * 8;

    for (int idx = tid; idx < 8 * HH; idx += 256) {
        int gg = idx >> 6, jj = idx & 63;
        sh[gg][jj] = g_h[(size_t)(nbase + gg) * HH + jj];
    }
    __syncthreads();

    float a = tb[k];
#pragma unroll
    for (int j = 0; j < HH; j++)
        a = fmaf(sh[g][j], tw[j * KK + k], a);
    // softplus(x) = log1p(exp(-|x|)) + max(x,0)
    out[(size_t)(nbase + g) * KK + k] = log1pf(__expf(-fabsf(a))) + fmaxf(a, 0.f);
}

// =====================================================================
extern "C" void kernel_launch(void* const* d_in, const int* in_sizes, int n_in,
                              void* d_out, int out_size) {
    const float* x      = (const float*)d_in[0];
    const int*   src    = (const int*)  d_in[1];
    const int*   dst    = (const int*)  d_in[2];
    const float* basew  = (const float*)d_in[3];
    const float* enc_w1 = (const float*)d_in[4];
    const float* enc_b1 = (const float*)d_in[5];
    const float* enc_w2 = (const float*)d_in[6];
    const float* enc_b2 = (const float*)d_in[7];
    const float* gw1    = (const float*)d_in[8];
    const float* gb1    = (const float*)d_in[9];
    const float* gw2    = (const float*)d_in[10];
    const float* gb2    = (const float*)d_in[11];
    const float* uw1    = (const float*)d_in[12];
    const float* ub1    = (const float*)d_in[13];
    const float* uw2    = (const float*)d_in[14];
    const float* ub2    = (const float*)d_in[15];
    const float* lng    = (const float*)d_in[16];
    const float* lnb    = (const float*)d_in[17];
    const float* rho    = (const float*)d_in[18];
    const float* tw     = (const float*)d_in[19];
    const float* tb     = (const float*)d_in[20];
    float* out = (float*)d_out;

    k_encoder<<<NN / 4, 256>>>(x, enc_w1, enc_b1, enc_w2, enc_b2);
    k_rho<<<(NN + 255) / 256, 256>>>(rho);

    for (int l = 0; l < LL; l++) {
        k_edge<<<2048, 256>>>(src, dst, basew, gw1, gb1, gw2, gb2);
        k_update<<<NN / 4, 256>>>(uw1 + l * HH * HH, ub1 + l * HH,
                                  uw2 + l * HH * HH, ub2 + l * HH,
                                  lng + l * HH, lnb + l * HH);
    }

    k_head<<<NN / 8, 256>>>(tw, tb, out);
}

// round 3
// speedup vs baseline: 3.4442x; 2.0702x over previous
#include <cuda_runtime.h>
#include <math.h>

#define NN 50000
#define CC 256
#define EE 800000
#define HH 64
#define KK 32
#define LL 2

// ---- scratch (no allocation allowed) ----
__device__ float g_h[NN * HH];     // node state
__device__ float g_m[NN * HH];     // scatter accumulator (zero-invariant between replays)
__device__ float g_deg[NN];        // weighted degree (zero-invariant between replays)
__device__ float g_rho[NN];        // sigmoid(rho_raw)
__device__ float g_a[NN * HH];     // per-node src-side gate projection: h @ W1[0:64]
__device__ float g_b[NN * HH];     // per-node dst-side gate projection: h @ W1[64:128] + b1

// =====================================================================
// Encoder: h = relu(relu(x @ W1 + b1) @ W2 + b2); then fused gate
// pre-projection a/b for layer 0.
// block = 256 threads = 4 nodes x 64 channels
// =====================================================================
__global__ void k_encoder(const float* __restrict__ x,
                          const float* __restrict__ w1, const float* __restrict__ b1,
                          const float* __restrict__ w2, const float* __restrict__ b2,
                          const float* __restrict__ gw1, const float* __restrict__ gb1) {
    __shared__ float sx[4][CC];
    __shared__ float sh1[4][HH];
    __shared__ float sh2[4][HH];
    int tid = threadIdx.x;
    int g = tid >> 6;        // node within block
    int j = tid & 63;        // channel
    int nbase = blockIdx.x * 4;

    for (int idx = tid; idx < 4 * CC; idx += 256) {
        int gg = idx / CC, c = idx % CC;
        sx[gg][c] = x[(size_t)(nbase + gg) * CC + c];
    }
    __syncthreads();

    float acc = b1[j];
#pragma unroll 8
    for (int c = 0; c < CC; c++)
        acc = fmaf(sx[g][c], w1[c * HH + j], acc);
    sh1[g][j] = fmaxf(acc, 0.f);
    __syncthreads();

    float acc2 = b2[j];
#pragma unroll
    for (int i = 0; i < HH; i++)
        acc2 = fmaf(sh1[g][i], w2[i * HH + j], acc2);
    float h = fmaxf(acc2, 0.f);
    size_t n = (size_t)(nbase + g);
    g_h[n * HH + j] = h;
    sh2[g][j] = h;
    __syncthreads();

    // gate pre-projection: a = h @ W1s ; b = h @ W1d + b1
    float aacc = 0.f, bacc = gb1[j];
#pragma unroll
    for (int i = 0; i < HH; i++) {
        float hv = sh2[g][i];
        aacc = fmaf(hv, gw1[i * HH + j], aacc);
        bacc = fmaf(hv, gw1[(i + HH) * HH + j], bacc);
    }
    g_a[n * HH + j] = aacc;
    g_b[n * HH + j] = bacc;
}

// =====================================================================
// rho = sigmoid(rho_raw)
// =====================================================================
__global__ void k_rho(const float* __restrict__ rho_raw) {
    int i = blockIdx.x * blockDim.x + threadIdx.x;
    if (i < NN) g_rho[i] = 1.f / (1.f + __expf(-rho_raw[i]));
}

// =====================================================================
// Edge kernel: warp per edge, using precomputed node projections.
//   z = relu(a[src] + b[dst])           (64 ch, 2/lane)
//   gate = sigmoid(z @ gate_w2 + gate_b2)
//   w = base_w * gate * rho[src]*rho[dst]
//   atomic: m[dst] += w*h_src ; deg[dst] += w
// =====================================================================
__global__ void __launch_bounds__(256) k_edge(
        const int* __restrict__ src, const int* __restrict__ dst,
        const float* __restrict__ basew,
        const float* __restrict__ gw2, const float* __restrict__ gb2) {
    __shared__ float sw2[64];
    __shared__ float sb2;
    int tid = threadIdx.x;
    if (tid < 64) sw2[tid] = gw2[tid];
    if (tid == 0) sb2 = gb2[0];
    __syncthreads();

    int lane = tid & 31;
    int warp = tid >> 5;
    int e = blockIdx.x * 8 + warp;          // grid = EE/8 exactly
    if (e >= EE) return;

    int s = __ldg(src + e), d = __ldg(dst + e);
    const float* ap = g_a + (size_t)s * HH;
    const float* bp = g_b + (size_t)d * HH;

    float zx = ap[lane]      + bp[lane];
    float zy = ap[lane + 32] + bp[lane + 32];
    float part = fmaxf(zx, 0.f) * sw2[lane] + fmaxf(zy, 0.f) * sw2[lane + 32];
#pragma unroll
    for (int off = 16; off; off >>= 1)
        part += __shfl_xor_sync(0xffffffffu, part, off);

    float gate = 1.f / (1.f + __expf(-(part + sb2)));
    float wt = __ldg(basew + e) * gate * g_rho[s] * g_rho[d];

    const float* hs = g_h + (size_t)s * HH;
    atomicAdd(&g_m[(size_t)d * HH + lane],      wt * hs[lane]);
    atomicAdd(&g_m[(size_t)d * HH + lane + 32], wt * hs[lane + 32]);
    if (lane == 0) atomicAdd(&g_deg[d], wt);
}

// =====================================================================
// Node update + LayerNorm (+ fused gate pre-projection for next layer).
// block = 256 = 4 nodes x 64 channels.
//   neigh = m/(deg+eps); u = relu(neigh@W1+b1)@W2+b2
//   h = LN(h + u) * g + b
// Resets g_m/g_deg to zero (replay invariant).
// =====================================================================
__global__ void k_update(const float* __restrict__ uw1, const float* __restrict__ ub1,
                         const float* __restrict__ uw2, const float* __restrict__ ub2,
                         const float* __restrict__ lng, const float* __restrict__ lnb,
                         const float* __restrict__ gw1, const float* __restrict__ gb1,
                         int do_pre) {
    __shared__ float sn[4][HH];
    __shared__ float st[4][HH];
    __shared__ float2 red[8];
    int tid = threadIdx.x;
    int g = tid >> 6;
    int j = tid & 63;
    int n = blockIdx.x * 4 + g;

    float deg = g_deg[n];
    float nb = g_m[(size_t)n * HH + j] / (deg + 1e-8f);
    sn[g][j] = nb;
    __syncthreads();

    // reset accumulators for next layer / next replay
    g_m[(size_t)n * HH + j] = 0.f;
    if (j == 0) g_deg[n] = 0.f;

    float a = ub1[j];
#pragma unroll
    for (int i = 0; i < HH; i++)
        a = fmaf(sn[g][i], uw1[i * HH + j], a);
    st[g][j] = fmaxf(a, 0.f);
    __syncthreads();

    float u = ub2[j];
#pragma unroll
    for (int i = 0; i < HH; i++)
        u = fmaf(st[g][i], uw2[i * HH + j], u);

    float pre = g_h[(size_t)n * HH + j] + u;

    float s1 = pre, s2 = pre * pre;
#pragma unroll
    for (int off = 16; off; off >>= 1) {
        s1 += __shfl_xor_sync(0xffffffffu, s1, off);
        s2 += __shfl_xor_sync(0xffffffffu, s2, off);
    }
    int warp = tid >> 5;
    if ((tid & 31) == 0) red[warp] = make_float2(s1, s2);
    __syncthreads();

    float tsum = red[g * 2].x + red[g * 2 + 1].x;
    float tsq  = red[g * 2].y + red[g * 2 + 1].y;
    float mean = tsum * (1.f / HH);
    float var  = tsq * (1.f / HH) - mean * mean;
    float inv  = rsqrtf(var + 1e-5f);
    float h = (pre - mean) * inv * lng[j] + lnb[j];
    g_h[(size_t)n * HH + j] = h;

    if (do_pre) {
        __syncthreads();          // sn no longer needed
        sn[g][j] = h;             // reuse smem for new h
        __syncthreads();
        float aacc = 0.f, bacc = gb1[j];
#pragma unroll
        for (int i = 0; i < HH; i++) {
            float hv = sn[g][i];
            aacc = fmaf(hv, gw1[i * HH + j], aacc);
            bacc = fmaf(hv, gw1[(i + HH) * HH + j], bacc);
        }
        g_a[(size_t)n * HH + j] = aacc;
        g_b[(size_t)n * HH + j] = bacc;
    }
}

// =====================================================================
// Head: U = softplus(h @ toU_w + toU_b). block = 256 = 8 nodes x 32.
// =====================================================================
__global__ void k_head(const float* __restrict__ tw, const float* __restrict__ tb,
                       float* __restrict__ out) {
    __shared__ float sh[8][HH];
    int tid = threadIdx.x;
    int g = tid >> 5;
    int k = tid & 31;
    int nbase = blockIdx.x * 8;

    for (int idx = tid; idx < 8 * HH; idx += 256) {
        int gg = idx >> 6, jj = idx & 63;
        sh[gg][jj] = g_h[(size_t)(nbase + gg) * HH + jj];
    }
    __syncthreads();

    float a = tb[k];
#pragma unroll
    for (int j = 0; j < HH; j++)
        a = fmaf(sh[g][j], tw[j * KK + k], a);
    out[(size_t)(nbase + g) * KK + k] = log1pf(__expf(-fabsf(a))) + fmaxf(a, 0.f);
}

// =====================================================================
extern "C" void kernel_launch(void* const* d_in, const int* in_sizes, int n_in,
                              void* d_out, int out_size) {
    const float* x      = (const float*)d_in[0];
    const int*   src    = (const int*)  d_in[1];
    const int*   dst    = (const int*)  d_in[2];
    const float* basew  = (const float*)d_in[3];
    const float* enc_w1 = (const float*)d_in[4];
    const float* enc_b1 = (const float*)d_in[5];
    const float* enc_w2 = (const float*)d_in[6];
    const float* enc_b2 = (const float*)d_in[7];
    const float* gw1    = (const float*)d_in[8];
    const float* gb1    = (const float*)d_in[9];
    const float* gw2    = (const float*)d_in[10];
    const float* gb2    = (const float*)d_in[11];
    const float* uw1    = (const float*)d_in[12];
    const float* ub1    = (const float*)d_in[13];
    const float* uw2    = (const float*)d_in[14];
    const float* ub2    = (const float*)d_in[15];
    const float* lng    = (const float*)d_in[16];
    const float* lnb    = (const float*)d_in[17];
    const float* rho    = (const float*)d_in[18];
    const float* tw     = (const float*)d_in[19];
    const float* tb     = (const float*)d_in[20];
    float* out = (float*)d_out;

    k_encoder<<<NN / 4, 256>>>(x, enc_w1, enc_b1, enc_w2, enc_b2, gw1, gb1);
    k_rho<<<(NN + 255) / 256, 256>>>(rho);

    for (int l = 0; l < LL; l++) {
        k_edge<<<EE / 8, 256>>>(src, dst, basew, gw2, gb2);
        k_update<<<NN / 4, 256>>>(uw1 + l * HH * HH, ub1 + l * HH,
                                  uw2 + l * HH * HH, ub2 + l * HH,
                                  lng + l * HH, lnb + l * HH,
                                  gw1, gb1, l < LL - 1 ? 1 : 0);
    }

    k_head<<<NN / 8, 256>>>(tw, tb, out);
}

// round 5
// speedup vs baseline: 5.1393x; 1.4922x over previous
#include <cuda_runtime.h>
#include <math.h>

#define NN 50000
#define CC 256
#define EE 800000
#define HH 64
#define KK 32
#define LL 2
#define NB 64   // nodes per block in tiled node kernels

// ---- scratch (no allocation allowed) ----
__device__ float g_h[NN * HH];     // node state
__device__ float g_m[NN * HH];     // scatter accumulator (zero-invariant between replays)
__device__ float g_deg[NN];        // weighted degree (zero-invariant between replays)
__device__ float g_rho[NN];        // sigmoid(rho_raw)
__device__ float g_a[NN * HH];     // per-node src-side gate projection: h @ W1[0:64]
__device__ float g_b[NN * HH];     // per-node dst-side gate projection: h @ W1[64:128] + b1

// 4x4 outer-product FMA tile: acc[n*4+c] += av.n * wv.c
__device__ __forceinline__ void mm16(const float4 av, const float4 wv, float* acc) {
    acc[0]  = fmaf(av.x, wv.x, acc[0]);  acc[1]  = fmaf(av.x, wv.y, acc[1]);
    acc[2]  = fmaf(av.x, wv.z, acc[2]);  acc[3]  = fmaf(av.x, wv.w, acc[3]);
    acc[4]  = fmaf(av.y, wv.x, acc[4]);  acc[5]  = fmaf(av.y, wv.y, acc[5]);
    acc[6]  = fmaf(av.y, wv.z, acc[6]);  acc[7]  = fmaf(av.y, wv.w, acc[7]);
    acc[8]  = fmaf(av.z, wv.x, acc[8]);  acc[9]  = fmaf(av.z, wv.y, acc[9]);
    acc[10] = fmaf(av.z, wv.z, acc[10]); acc[11] = fmaf(av.z, wv.w, acc[11]);
    acc[12] = fmaf(av.w, wv.x, acc[12]); acc[13] = fmaf(av.w, wv.y, acc[13]);
    acc[14] = fmaf(av.w, wv.z, acc[14]); acc[15] = fmaf(av.w, wv.w, acc[15]);
}

__device__ __forceinline__ void zero16(float* acc) {
#pragma unroll
    for (int k = 0; k < 16; k++) acc[k] = 0.f;
}

// stage a 64x64 row-major global matrix into sW[64][68]
#define STAGE_W(sW, gptr) do {                                            \
    _Pragma("unroll")                                                     \
    for (int _q = 0; _q < 4; _q++) {                                      \
        int _lin = _q * 256 + tid;                                        \
        *(float4*)&sW[_lin >> 4][(_lin & 15) * 4] =                       \
            *(const float4*)&(gptr)[_lin * 4];                            \
    }                                                                     \
} while (0)

// tiled matvec: acc[16] += sA(64 x nodes) x sW(64 x ch) tile at (ng, cg)
#define MATVEC(sA, sW, acc) do {                                          \
    _Pragma("unroll 8")                                                   \
    for (int _i = 0; _i < 64; _i++) {                                     \
        float4 _av = *(float4*)&sA[_i][ng * 4];                           \
        float4 _wv = *(float4*)&sW[_i][cg * 4];                           \
        mm16(_av, _wv, acc);                                              \
    }                                                                     \
} while (0)

// =====================================================================
// Encoder (tiled): h = relu(relu(x @ W1 + b1) @ W2 + b2), then fused
// gate pre-projections a = h@gW1[0:64], b = h@gW1[64:128]+gb1.
// block = 256 threads = 16 node-groups x 16 channel-groups, 64 nodes/block
// =====================================================================
__global__ void __launch_bounds__(256) k_encoder(
        const float* __restrict__ x,
        const float* __restrict__ w1, const float* __restrict__ b1,
        const float* __restrict__ w2, const float* __restrict__ b2,
        const float* __restrict__ gw1, const float* __restrict__ gb1) {
    __shared__ float sA[64][NB + 4];
    __shared__ float sW[64][68];
    int tid = threadIdx.x;
    int cg = tid & 15, ng = tid >> 4;
    int n0 = blockIdx.x * NB;

    float acc[16];
    zero16(acc);

    // ---- layer1: K=256 in 4 chunks of 64 ----
    for (int kb = 0; kb < 4; kb++) {
#pragma unroll
        for (int q = 0; q < 4; q++) {
            int lin = q * 256 + tid;
            int node = lin >> 4;
            int c4 = (lin & 15) * 4;
            int n = n0 + node;
            float4 v = make_float4(0.f, 0.f, 0.f, 0.f);
            if (n < NN) v = *(const float4*)&x[(size_t)n * CC + kb * 64 + c4];
            sA[c4 + 0][node] = v.x; sA[c4 + 1][node] = v.y;
            sA[c4 + 2][node] = v.z; sA[c4 + 3][node] = v.w;
        }
        STAGE_W(sW, w1 + (size_t)kb * 64 * HH);
        __syncthreads();
        MATVEC(sA, sW, acc);
        __syncthreads();
    }

    // h1 = relu(acc + b1); write transposed into sA, stage w2
    {
        float4 bv = *(const float4*)&b1[cg * 4];
        float bb[4] = {bv.x, bv.y, bv.z, bv.w};
#pragma unroll
        for (int n = 0; n < 4; n++)
#pragma unroll
            for (int c = 0; c < 4; c++)
                sA[cg * 4 + c][ng * 4 + n] = fmaxf(acc[n * 4 + c] + bb[c], 0.f);
    }
    STAGE_W(sW, w2);
    __syncthreads();

    zero16(acc);
    MATVEC(sA, sW, acc);
    __syncthreads();

    // h = relu(acc + b2); store, write transposed into sA
    float hval[16];
    {
        float4 bv = *(const float4*)&b2[cg * 4];
        float bb[4] = {bv.x, bv.y, bv.z, bv.w};
#pragma unroll
        for (int n = 0; n < 4; n++) {
            int node = n0 + ng * 4 + n;
#pragma unroll
            for (int c = 0; c < 4; c++) {
                hval[n * 4 + c] = fmaxf(acc[n * 4 + c] + bb[c], 0.f);
                sA[cg * 4 + c][ng * 4 + n] = hval[n * 4 + c];
            }
            if (node < NN)
                *(float4*)&g_h[(size_t)node * HH + cg * 4] =
                    make_float4(hval[n*4], hval[n*4+1], hval[n*4+2], hval[n*4+3]);
        }
    }
    STAGE_W(sW, gw1);                 // first 64 rows of gate W1
    __syncthreads();

    zero16(acc);
    MATVEC(sA, sW, acc);
#pragma unroll
    for (int n = 0; n < 4; n++) {
        int node = n0 + ng * 4 + n;
        if (node < NN)
            *(float4*)&g_a[(size_t)node * HH + cg * 4] =
                make_float4(acc[n*4], acc[n*4+1], acc[n*4+2], acc[n*4+3]);
    }
    __syncthreads();
    STAGE_W(sW, gw1 + (size_t)64 * HH);  // second 64 rows
    __syncthreads();

    zero16(acc);
    MATVEC(sA, sW, acc);
    {
        float4 bv = *(const float4*)&gb1[cg * 4];
        float bb[4] = {bv.x, bv.y, bv.z, bv.w};
#pragma unroll
        for (int n = 0; n < 4; n++) {
            int node = n0 + ng * 4 + n;
            if (node < NN)
                *(float4*)&g_b[(size_t)node * HH + cg * 4] =
                    make_float4(acc[n*4] + bb[0], acc[n*4+1] + bb[1],
                                acc[n*4+2] + bb[2], acc[n*4+3] + bb[3]);
        }
    }
}

// =====================================================================
// rho = sigmoid(rho_raw)
// =====================================================================
__global__ void k_rho(const float* __restrict__ rho_raw) {
    int i = blockIdx.x * blockDim.x + threadIdx.x;
    if (i < NN) g_rho[i] = 1.f / (1.f + __expf(-rho_raw[i]));
}

// =====================================================================
// Edge kernel: warp per edge, using precomputed node projections.
// =====================================================================
__global__ void __launch_bounds__(256) k_edge(
        const int* __restrict__ src, const int* __restrict__ dst,
        const float* __restrict__ basew,
        const float* __restrict__ gw2, const float* __restrict__ gb2) {
    __shared__ float sw2[64];
    __shared__ float sb2;
    int tid = threadIdx.x;
    if (tid < 64) sw2[tid] = gw2[tid];
    if (tid == 0) sb2 = gb2[0];
    __syncthreads();

    int lane = tid & 31;
    int warp = tid >> 5;
    int e = blockIdx.x * 8 + warp;          // grid = EE/8 exactly
    if (e >= EE) return;

    int s = __ldg(src + e), d = __ldg(dst + e);
    const float* ap = g_a + (size_t)s * HH;
    const float* bp = g_b + (size_t)d * HH;

    float zx = ap[lane]      + bp[lane];
    float zy = ap[lane + 32] + bp[lane + 32];
    float part = fmaxf(zx, 0.f) * sw2[lane] + fmaxf(zy, 0.f) * sw2[lane + 32];
#pragma unroll
    for (int off = 16; off; off >>= 1)
        part += __shfl_xor_sync(0xffffffffu, part, off);

    float gate = 1.f / (1.f + __expf(-(part + sb2)));
    float wt = __ldg(basew + e) * gate * g_rho[s] * g_rho[d];

    const float* hs = g_h + (size_t)s * HH;
    atomicAdd(&g_m[(size_t)d * HH + lane],      wt * hs[lane]);
    atomicAdd(&g_m[(size_t)d * HH + lane + 32], wt * hs[lane + 32]);
    if (lane == 0) atomicAdd(&g_deg[d], wt);
}

// =====================================================================
// Node update (tiled) + LayerNorm (+ fused gate pre-projection).
// block = 256 threads, 64 nodes/block. Resets g_m/g_deg (replay invariant).
// =====================================================================
__global__ void __launch_bounds__(256) k_update(
        const float* __restrict__ uw1, const float* __restrict__ ub1,
        const float* __restrict__ uw2, const float* __restrict__ ub2,
        const float* __restrict__ lng, const float* __restrict__ lnb,
        const float* __restrict__ gw1, const float* __restrict__ gb1,
        int do_pre) {
    __shared__ float sA[64][NB + 4];
    __shared__ float sW[64][68];
    __shared__ float sInv[NB];
    int tid = threadIdx.x;
    int cg = tid & 15, ng = tid >> 4;
    int n0 = blockIdx.x * NB;

    if (tid < NB) {
        int n = n0 + tid;
        float deg = (n < NN) ? g_deg[n] : 0.f;
        sInv[tid] = 1.f / (deg + 1e-8f);
        if (n < NN) g_deg[n] = 0.f;
    }
    __syncthreads();

    // stage neigh = m*inv transposed; reset g_m; stage uw1
#pragma unroll
    for (int q = 0; q < 4; q++) {
        int lin = q * 256 + tid;
        int node = lin >> 4;
        int c4 = (lin & 15) * 4;
        int n = n0 + node;
        float4 v = make_float4(0.f, 0.f, 0.f, 0.f);
        if (n < NN) {
            v = *(const float4*)&g_m[(size_t)n * HH + c4];
            *(float4*)&g_m[(size_t)n * HH + c4] = make_float4(0.f, 0.f, 0.f, 0.f);
        }
        float inv = sInv[node];
        sA[c4 + 0][node] = v.x * inv; sA[c4 + 1][node] = v.y * inv;
        sA[c4 + 2][node] = v.z * inv; sA[c4 + 3][node] = v.w * inv;
    }
    STAGE_W(sW, uw1);
    __syncthreads();

    float acc[16];
    zero16(acc);
    MATVEC(sA, sW, acc);
    __syncthreads();

    // t = relu(acc + ub1) -> transposed into sA; stage uw2
    {
        float4 bv = *(const float4*)&ub1[cg * 4];
        float bb[4] = {bv.x, bv.y, bv.z, bv.w};
#pragma unroll
        for (int n = 0; n < 4; n++)
#pragma unroll
            for (int c = 0; c < 4; c++)
                sA[cg * 4 + c][ng * 4 + n] = fmaxf(acc[n * 4 + c] + bb[c], 0.f);
    }
    STAGE_W(sW, uw2);
    __syncthreads();

    zero16(acc);
    MATVEC(sA, sW, acc);

    // pre = h + u; LayerNorm per node (reduce over 16 cg-threads)
    float pre[16];
    {
        float4 bv = *(const float4*)&ub2[cg * 4];
        float bb[4] = {bv.x, bv.y, bv.z, bv.w};
#pragma unroll
        for (int n = 0; n < 4; n++) {
            int node = n0 + ng * 4 + n;
            float4 h4 = make_float4(0.f, 0.f, 0.f, 0.f);
            if (node < NN) h4 = *(const float4*)&g_h[(size_t)node * HH + cg * 4];
            pre[n * 4 + 0] = h4.x + acc[n * 4 + 0] + bb[0];
            pre[n * 4 + 1] = h4.y + acc[n * 4 + 1] + bb[1];
            pre[n * 4 + 2] = h4.z + acc[n * 4 + 2] + bb[2];
            pre[n * 4 + 3] = h4.w + acc[n * 4 + 3] + bb[3];
        }
    }
    float4 gv = *(const float4*)&lng[cg * 4];
    float4 bv = *(const float4*)&lnb[cg * 4];
    float hn[16];
#pragma unroll
    for (int n = 0; n < 4; n++) {
        float s1 = pre[n*4] + pre[n*4+1] + pre[n*4+2] + pre[n*4+3];
        float s2 = pre[n*4]*pre[n*4] + pre[n*4+1]*pre[n*4+1]
                 + pre[n*4+2]*pre[n*4+2] + pre[n*4+3]*pre[n*4+3];
#pragma unroll
        for (int m = 1; m < 16; m <<= 1) {
            s1 += __shfl_xor_sync(0xffffffffu, s1, m);
            s2 += __shfl_xor_sync(0xffffffffu, s2, m);
        }
        float mean = s1 * (1.f / HH);
        float var  = s2 * (1.f / HH) - mean * mean;
        float inv  = rsqrtf(var + 1e-5f);
        hn[n*4+0] = (pre[n*4+0] - mean) * inv * gv.x + bv.x;
        hn[n*4+1] = (pre[n*4+1] - mean) * inv * gv.y + bv.y;
        hn[n*4+2] = (pre[n*4+2] - mean) * inv * gv.z + bv.z;
        hn[n*4+3] = (pre[n*4+3] - mean) * inv * gv.w + bv.w;
        int node = n0 + ng * 4 + n;
        if (node < NN)
            *(float4*)&g_h[(size_t)node * HH + cg * 4] =
                make_float4(hn[n*4], hn[n*4+1], hn[n*4+2], hn[n*4+3]);
    }

    if (do_pre) {
        __syncthreads();   // all reads of sA/sW done
#pragma unroll
        for (int n = 0; n < 4; n++)
#pragma unroll
            for (int c = 0; c < 4; c++)
                sA[cg * 4 + c][ng * 4 + n] = hn[n * 4 + c];
        STAGE_W(sW, gw1);
        __syncthreads();

        zero16(acc);
        MATVEC(sA, sW, acc);
#pragma unroll
        for (int n = 0; n < 4; n++) {
            int node = n0 + ng * 4 + n;
            if (node < NN)
                *(float4*)&g_a[(size_t)node * HH + cg * 4] =
                    make_float4(acc[n*4], acc[n*4+1], acc[n*4+2], acc[n*4+3]);
        }
        __syncthreads();
        STAGE_W(sW, gw1 + (size_t)64 * HH);
        __syncthreads();

        zero16(acc);
        MATVEC(sA, sW, acc);
        float4 gbv = *(const float4*)&gb1[cg * 4];
        float gb[4] = {gbv.x, gbv.y, gbv.z, gbv.w};
#pragma unroll
        for (int n = 0; n < 4; n++) {
            int node = n0 + ng * 4 + n;
            if (node < NN)
                *(float4*)&g_b[(size_t)node * HH + cg * 4] =
                    make_float4(acc[n*4] + gb[0], acc[n*4+1] + gb[1],
                                acc[n*4+2] + gb[2], acc[n*4+3] + gb[3]);
        }
    }
}

// =====================================================================
// Head: U = softplus(h @ toU_w + toU_b). block = 256 = 8 nodes x 32.
// =====================================================================
__global__ void k_head(const float* __restrict__ tw, const float* __restrict__ tb,
                       float* __restrict__ out) {
    __shared__ float sh[8][HH];
    int tid = threadIdx.x;
    int g = tid >> 5;
    int k = tid & 31;
    int nbase = blockIdx.x * 8;

    for (int idx = tid; idx < 8 * HH; idx += 256) {
        int gg = idx >> 6, jj = idx & 63;
        sh[gg][jj] = g_h[(size_t)(nbase + gg) * HH + jj];
    }
    __syncthreads();

    float a = tb[k];
#pragma unroll
    for (int j = 0; j < HH; j++)
        a = fmaf(sh[g][j], tw[j * KK + k], a);
    out[(size_t)(nbase + g) * KK + k] = log1pf(__expf(-fabsf(a))) + fmaxf(a, 0.f);
}

// =====================================================================
extern "C" void kernel_launch(void* const* d_in, const int* in_sizes, int n_in,
                              void* d_out, int out_size) {
    const float* x      = (const float*)d_in[0];
    const int*   src    = (const int*)  d_in[1];
    const int*   dst    = (const int*)  d_in[2];
    const float* basew  = (const float*)d_in[3];
    const float* enc_w1 = (const float*)d_in[4];
    const float* enc_b1 = (const float*)d_in[5];
    const float* enc_w2 = (const float*)d_in[6];
    const float* enc_b2 = (const float*)d_in[7];
    const float* gw1    = (const float*)d_in[8];
    const float* gb1    = (const float*)d_in[9];
    const float* gw2    = (const float*)d_in[10];
    const float* gb2    = (const float*)d_in[11];
    const float* uw1    = (const float*)d_in[12];
    const float* ub1    = (const float*)d_in[13];
    const float* uw2    = (const float*)d_in[14];
    const float* ub2    = (const float*)d_in[15];
    const float* lng    = (const float*)d_in[16];
    const float* lnb    = (const float*)d_in[17];
    const float* rho    = (const float*)d_in[18];
    const float* tw     = (const float*)d_in[19];
    const float* tb     = (const float*)d_in[20];
    float* out = (float*)d_out;

    int nblocks = (NN + NB - 1) / NB;
    k_encoder<<<nblocks, 256>>>(x, enc_w1, enc_b1, enc_w2, enc_b2, gw1, gb1);
    k_rho<<<(NN + 255) / 256, 256>>>(rho);

    for (int l = 0; l < LL; l++) {
        k_edge<<<EE / 8, 256>>>(src, dst, basew, gw2, gb2);
        k_update<<<nblocks, 256>>>(uw1 + l * HH * HH, ub1 + l * HH,
                                   uw2 + l * HH * HH, ub2 + l * HH,
                                   lng + l * HH, lnb + l * HH,
                                   gw1, gb1, l < LL - 1 ? 1 : 0);
    }

    k_head<<<NN / 8, 256>>>(tw, tb, out);
}

// round 7
// speedup vs baseline: 6.1760x; 1.2017x over previous
#include <cuda_runtime.h>
#include <math.h>

#define NN 50000
#define CC 256
#define EE 800000
#define HH 64
#define KK 32
#define LL 2
#define NB 64   // nodes per block in tiled node kernels

// ---- scratch (no allocation allowed) ----
__device__ float g_h[NN * HH];     // node state
__device__ float g_m[NN * HH];     // scatter accumulator (zero-invariant between replays)
__device__ float g_deg[NN];        // weighted degree (zero-invariant between replays)
__device__ float g_rho[NN];        // sigmoid(rho_raw)
__device__ float g_a[NN * HH];     // per-node src-side gate projection: h @ W1[0:64]
__device__ float g_b[NN * HH];     // per-node dst-side gate projection: h @ W1[64:128] + b1

// 4x4 outer-product FMA tile: acc[n*4+c] += av.n * wv.c
__device__ __forceinline__ void mm16(const float4 av, const float4 wv, float* acc) {
    acc[0]  = fmaf(av.x, wv.x, acc[0]);  acc[1]  = fmaf(av.x, wv.y, acc[1]);
    acc[2]  = fmaf(av.x, wv.z, acc[2]);  acc[3]  = fmaf(av.x, wv.w, acc[3]);
    acc[4]  = fmaf(av.y, wv.x, acc[4]);  acc[5]  = fmaf(av.y, wv.y, acc[5]);
    acc[6]  = fmaf(av.y, wv.z, acc[6]);  acc[7]  = fmaf(av.y, wv.w, acc[7]);
    acc[8]  = fmaf(av.z, wv.x, acc[8]);  acc[9]  = fmaf(av.z, wv.y, acc[9]);
    acc[10] = fmaf(av.z, wv.z, acc[10]); acc[11] = fmaf(av.z, wv.w, acc[11]);
    acc[12] = fmaf(av.w, wv.x, acc[12]); acc[13] = fmaf(av.w, wv.y, acc[13]);
    acc[14] = fmaf(av.w, wv.z, acc[14]); acc[15] = fmaf(av.w, wv.w, acc[15]);
}

__device__ __forceinline__ void zero16(float* acc) {
#pragma unroll
    for (int k = 0; k < 16; k++) acc[k] = 0.f;
}

__device__ __forceinline__ void red_v2(float* addr, float vx, float vy) {
    asm volatile("red.global.add.v2.f32 [%0], {%1, %2};"
                 :: "l"(addr), "f"(vx), "f"(vy) : "memory");
}

// stage a 64x64 row-major global matrix into sW[64][68]
#define STAGE_W(sW, gptr) do {                                            \
    _Pragma("unroll")                                                     \
    for (int _q = 0; _q < 4; _q++) {                                      \
        int _lin = _q * 256 + tid;                                        \
        *(float4*)&sW[_lin >> 4][(_lin & 15) * 4] =                       \
            *(const float4*)&(gptr)[_lin * 4];                            \
    }                                                                     \
} while (0)

// tiled matvec: acc[16] += sA(64 x nodes) x sW(64 x ch) tile at (ng, cg)
#define MATVEC(sA, sW, acc) do {                                          \
    _Pragma("unroll 8")                                                   \
    for (int _i = 0; _i < 64; _i++) {                                     \
        float4 _av = *(float4*)&sA[_i][ng * 4];                           \
        float4 _wv = *(float4*)&sW[_i][cg * 4];                           \
        mm16(_av, _wv, acc);                                              \
    }                                                                     \
} while (0)

// =====================================================================
// Encoder (tiled): h = relu(relu(x @ W1 + b1) @ W2 + b2), then fused
// gate pre-projections a = h@gW1[0:64], b = h@gW1[64:128]+gb1.
// block = 256 threads = 16 node-groups x 16 channel-groups, 64 nodes/block
// =====================================================================
__global__ void __launch_bounds__(256) k_encoder(
        const float* __restrict__ x,
        const float* __restrict__ w1, const float* __restrict__ b1,
        const float* __restrict__ w2, const float* __restrict__ b2,
        const float* __restrict__ gw1, const float* __restrict__ gb1) {
    __shared__ float sA[64][NB + 4];
    __shared__ float sW[64][68];
    int tid = threadIdx.x;
    int cg = tid & 15, ng = tid >> 4;
    int n0 = blockIdx.x * NB;

    float acc[16];
    zero16(acc);

    // ---- layer1: K=256 in 4 chunks of 64 ----
    for (int kb = 0; kb < 4; kb++) {
#pragma unroll
        for (int q = 0; q < 4; q++) {
            int lin = q * 256 + tid;
            int node = lin >> 4;
            int c4 = (lin & 15) * 4;
            int n = n0 + node;
            float4 v = make_float4(0.f, 0.f, 0.f, 0.f);
            if (n < NN) v = *(const float4*)&x[(size_t)n * CC + kb * 64 + c4];
            sA[c4 + 0][node] = v.x; sA[c4 + 1][node] = v.y;
            sA[c4 + 2][node] = v.z; sA[c4 + 3][node] = v.w;
        }
        STAGE_W(sW, w1 + (size_t)kb * 64 * HH);
        __syncthreads();
        MATVEC(sA, sW, acc);
        __syncthreads();
    }

    // h1 = relu(acc + b1); write transposed into sA, stage w2
    {
        float4 bv = *(const float4*)&b1[cg * 4];
        float bb[4] = {bv.x, bv.y, bv.z, bv.w};
#pragma unroll
        for (int n = 0; n < 4; n++)
#pragma unroll
            for (int c = 0; c < 4; c++)
                sA[cg * 4 + c][ng * 4 + n] = fmaxf(acc[n * 4 + c] + bb[c], 0.f);
    }
    STAGE_W(sW, w2);
    __syncthreads();

    zero16(acc);
    MATVEC(sA, sW, acc);
    __syncthreads();

    // h = relu(acc + b2); store, write transposed into sA
    float hval[16];
    {
        float4 bv = *(const float4*)&b2[cg * 4];
        float bb[4] = {bv.x, bv.y, bv.z, bv.w};
#pragma unroll
        for (int n = 0; n < 4; n++) {
            int node = n0 + ng * 4 + n;
#pragma unroll
            for (int c = 0; c < 4; c++) {
                hval[n * 4 + c] = fmaxf(acc[n * 4 + c] + bb[c], 0.f);
                sA[cg * 4 + c][ng * 4 + n] = hval[n * 4 + c];
            }
            if (node < NN)
                *(float4*)&g_h[(size_t)node * HH + cg * 4] =
                    make_float4(hval[n*4], hval[n*4+1], hval[n*4+2], hval[n*4+3]);
        }
    }
    STAGE_W(sW, gw1);                 // first 64 rows of gate W1
    __syncthreads();

    zero16(acc);
    MATVEC(sA, sW, acc);
#pragma unroll
    for (int n = 0; n < 4; n++) {
        int node = n0 + ng * 4 + n;
        if (node < NN)
            *(float4*)&g_a[(size_t)node * HH + cg * 4] =
                make_float4(acc[n*4], acc[n*4+1], acc[n*4+2], acc[n*4+3]);
    }
    __syncthreads();
    STAGE_W(sW, gw1 + (size_t)64 * HH);  // second 64 rows
    __syncthreads();

    zero16(acc);
    MATVEC(sA, sW, acc);
    {
        float4 bv = *(const float4*)&gb1[cg * 4];
        float bb[4] = {bv.x, bv.y, bv.z, bv.w};
#pragma unroll
        for (int n = 0; n < 4; n++) {
            int node = n0 + ng * 4 + n;
            if (node < NN)
                *(float4*)&g_b[(size_t)node * HH + cg * 4] =
                    make_float4(acc[n*4] + bb[0], acc[n*4+1] + bb[1],
                                acc[n*4+2] + bb[2], acc[n*4+3] + bb[3]);
        }
    }
}

// =====================================================================
// rho = sigmoid(rho_raw)
// =====================================================================
__global__ void k_rho(const float* __restrict__ rho_raw) {
    int i = blockIdx.x * blockDim.x + threadIdx.x;
    if (i < NN) g_rho[i] = 1.f / (1.f + __expf(-rho_raw[i]));
}

// =====================================================================
// Edge kernel: warp per 4 edges; lane owns channels (2*lane, 2*lane+1).
//   z = relu(a[src] + b[dst]); gate = sigmoid(z @ w2 + b2)
//   w = base_w * gate * rho[src]*rho[dst]
//   red.v2: m[dst] += w*h_src ; deg[dst] += w
// grid = EE/32 exactly (800000 / 32 = 25000)
// =====================================================================
__global__ void __launch_bounds__(256) k_edge(
        const int* __restrict__ src, const int* __restrict__ dst,
        const float* __restrict__ basew,
        const float* __restrict__ gw2, const float* __restrict__ gb2) {
    __shared__ float2 sw2[32];
    __shared__ float sb2;
    int tid = threadIdx.x;
    if (tid < 32) sw2[tid] = *(const float2*)&gw2[tid * 2];
    if (tid == 0) sb2 = gb2[0];
    __syncthreads();

    int lane = tid & 31;
    int warp = tid >> 5;
    int e0 = (blockIdx.x * 8 + warp) * 4;

    // vector loads of edge metadata (e0 is 4-aligned)
    int4 s4 = *(const int4*)&src[e0];
    int4 d4 = *(const int4*)&dst[e0];
    float4 bw4 = *(const float4*)&basew[e0];
    int sA[4] = {s4.x, s4.y, s4.z, s4.w};
    int dA[4] = {d4.x, d4.y, d4.z, d4.w};
    float bwA[4] = {bw4.x, bw4.y, bw4.z, bw4.w};

    float2 av[4], bv[4], hv[4];
#pragma unroll
    for (int t = 0; t < 4; t++) {
        av[t] = *(const float2*)&g_a[(size_t)sA[t] * HH + lane * 2];
        bv[t] = *(const float2*)&g_b[(size_t)dA[t] * HH + lane * 2];
        hv[t] = *(const float2*)&g_h[(size_t)sA[t] * HH + lane * 2];
    }

    float2 w2v = sw2[lane];
    float part[4];
#pragma unroll
    for (int t = 0; t < 4; t++)
        part[t] = fmaxf(av[t].x + bv[t].x, 0.f) * w2v.x
                + fmaxf(av[t].y + bv[t].y, 0.f) * w2v.y;

#pragma unroll
    for (int off = 16; off; off >>= 1)
#pragma unroll
        for (int t = 0; t < 4; t++)
            part[t] += __shfl_xor_sync(0xffffffffu, part[t], off);

#pragma unroll
    for (int t = 0; t < 4; t++) {
        float gate = 1.f / (1.f + __expf(-(part[t] + sb2)));
        float wt = bwA[t] * gate * g_rho[sA[t]] * g_rho[dA[t]];
        red_v2(&g_m[(size_t)dA[t] * HH + lane * 2], wt * hv[t].x, wt * hv[t].y);
        if (lane == 0) atomicAdd(&g_deg[dA[t]], wt);
    }
}

// =====================================================================
// Node update (tiled) + LayerNorm (+ fused gate pre-projection).
// block = 256 threads, 64 nodes/block. Resets g_m/g_deg (replay invariant).
// =====================================================================
__global__ void __launch_bounds__(256) k_update(
        const float* __restrict__ uw1, const float* __restrict__ ub1,
        const float* __restrict__ uw2, const float* __restrict__ ub2,
        const float* __restrict__ lng, const float* __restrict__ lnb,
        const float* __restrict__ gw1, const float* __restrict__ gb1,
        int do_pre) {
    __shared__ float sA[64][NB + 4];
    __shared__ float sW[64][68];
    __shared__ float sInv[NB];
    int tid = threadIdx.x;
    int cg = tid & 15, ng = tid >> 4;
    int n0 = blockIdx.x * NB;

    if (tid < NB) {
        int n = n0 + tid;
        float deg = (n < NN) ? g_deg[n] : 0.f;
        sInv[tid] = 1.f / (deg + 1e-8f);
        if (n < NN) g_deg[n] = 0.f;
    }
    __syncthreads();

    // stage neigh = m*inv transposed; reset g_m; stage uw1
#pragma unroll
    for (int q = 0; q < 4; q++) {
        int lin = q * 256 + tid;
        int node = lin >> 4;
        int c4 = (lin & 15) * 4;
        int n = n0 + node;
        float4 v = make_float4(0.f, 0.f, 0.f, 0.f);
        if (n < NN) {
            v = *(const float4*)&g_m[(size_t)n * HH + c4];
            *(float4*)&g_m[(size_t)n * HH + c4] = make_float4(0.f, 0.f, 0.f, 0.f);
        }
        float inv = sInv[node];
        sA[c4 + 0][node] = v.x * inv; sA[c4 + 1][node] = v.y * inv;
        sA[c4 + 2][node] = v.z * inv; sA[c4 + 3][node] = v.w * inv;
    }
    STAGE_W(sW, uw1);
    __syncthreads();

    float acc[16];
    zero16(acc);
    MATVEC(sA, sW, acc);
    __syncthreads();

    // t = relu(acc + ub1) -> transposed into sA; stage uw2
    {
        float4 bv = *(const float4*)&ub1[cg * 4];
        float bb[4] = {bv.x, bv.y, bv.z, bv.w};
#pragma unroll
        for (int n = 0; n < 4; n++)
#pragma unroll
            for (int c = 0; c < 4; c++)
                sA[cg * 4 + c][ng * 4 + n] = fmaxf(acc[n * 4 + c] + bb[c], 0.f);
    }
    STAGE_W(sW, uw2);
    __syncthreads();

    zero16(acc);
    MATVEC(sA, sW, acc);

    // pre = h + u; LayerNorm per node (reduce over 16 cg-threads)
    float pre[16];
    {
        float4 bv = *(const float4*)&ub2[cg * 4];
        float bb[4] = {bv.x, bv.y, bv.z, bv.w};
#pragma unroll
        for (int n = 0; n < 4; n++) {
            int node = n0 + ng * 4 + n;
            float4 h4 = make_float4(0.f, 0.f, 0.f, 0.f);
            if (node < NN) h4 = *(const float4*)&g_h[(size_t)node * HH + cg * 4];
            pre[n * 4 + 0] = h4.x + acc[n * 4 + 0] + bb[0];
            pre[n * 4 + 1] = h4.y + acc[n * 4 + 1] + bb[1];
            pre[n * 4 + 2] = h4.z + acc[n * 4 + 2] + bb[2];
            pre[n * 4 + 3] = h4.w + acc[n * 4 + 3] + bb[3];
        }
    }
    float4 gv = *(const float4*)&lng[cg * 4];
    float4 bv = *(const float4*)&lnb[cg * 4];
    float hn[16];
#pragma unroll
    for (int n = 0; n < 4; n++) {
        float s1 = pre[n*4] + pre[n*4+1] + pre[n*4+2] + pre[n*4+3];
        float s2 = pre[n*4]*pre[n*4] + pre[n*4+1]*pre[n*4+1]
                 + pre[n*4+2]*pre[n*4+2] + pre[n*4+3]*pre[n*4+3];
#pragma unroll
        for (int m = 1; m < 16; m <<= 1) {
            s1 += __shfl_xor_sync(0xffffffffu, s1, m);
            s2 += __shfl_xor_sync(0xffffffffu, s2, m);
        }
        float mean = s1 * (1.f / HH);
        float var  = s2 * (1.f / HH) - mean * mean;
        float inv  = rsqrtf(var + 1e-5f);
        hn[n*4+0] = (pre[n*4+0] - mean) * inv * gv.x + bv.x;
        hn[n*4+1] = (pre[n*4+1] - mean) * inv * gv.y + bv.y;
        hn[n*4+2] = (pre[n*4+2] - mean) * inv * gv.z + bv.z;
        hn[n*4+3] = (pre[n*4+3] - mean) * inv * gv.w + bv.w;
        int node = n0 + ng * 4 + n;
        if (node < NN)
            *(float4*)&g_h[(size_t)node * HH + cg * 4] =
                make_float4(hn[n*4], hn[n*4+1], hn[n*4+2], hn[n*4+3]);
    }

    if (do_pre) {
        __syncthreads();   // all reads of sA/sW done
#pragma unroll
        for (int n = 0; n < 4; n++)
#pragma unroll
            for (int c = 0; c < 4; c++)
                sA[cg * 4 + c][ng * 4 + n] = hn[n * 4 + c];
        STAGE_W(sW, gw1);
        __syncthreads();

        zero16(acc);
        MATVEC(sA, sW, acc);
#pragma unroll
        for (int n = 0; n < 4; n++) {
            int node = n0 + ng * 4 + n;
            if (node < NN)
                *(float4*)&g_a[(size_t)node * HH + cg * 4] =
                    make_float4(acc[n*4], acc[n*4+1], acc[n*4+2], acc[n*4+3]);
        }
        __syncthreads();
        STAGE_W(sW, gw1 + (size_t)64 * HH);
        __syncthreads();

        zero16(acc);
        MATVEC(sA, sW, acc);
        float4 gbv = *(const float4*)&gb1[cg * 4];
        float gb[4] = {gbv.x, gbv.y, gbv.z, gbv.w};
#pragma unroll
        for (int n = 0; n < 4; n++) {
            int node = n0 + ng * 4 + n;
            if (node < NN)
                *(float4*)&g_b[(size_t)node * HH + cg * 4] =
                    make_float4(acc[n*4] + gb[0], acc[n*4+1] + gb[1],
                                acc[n*4+2] + gb[2], acc[n*4+3] + gb[3]);
        }
    }
}

// =====================================================================
// Head: U = softplus(h @ toU_w + toU_b). block = 256 = 8 nodes x 32.
// =====================================================================
__global__ void k_head(const float* __restrict__ tw, const float* __restrict__ tb,
                       float* __restrict__ out) {
    __shared__ float sh[8][HH];
    int tid = threadIdx.x;
    int g = tid >> 5;
    int k = tid & 31;
    int nbase = blockIdx.x * 8;

    for (int idx = tid; idx < 8 * HH; idx += 256) {
        int gg = idx >> 6, jj = idx & 63;
        sh[gg][jj] = g_h[(size_t)(nbase + gg) * HH + jj];
    }
    __syncthreads();

    float a = tb[k];
#pragma unroll
    for (int j = 0; j < HH; j++)
        a = fmaf(sh[g][j], tw[j * KK + k], a);
    out[(size_t)(nbase + g) * KK + k] = log1pf(__expf(-fabsf(a))) + fmaxf(a, 0.f);
}

// =====================================================================
extern "C" void kernel_launch(void* const* d_in, const int* in_sizes, int n_in,
                              void* d_out, int out_size) {
    const float* x      = (const float*)d_in[0];
    const int*   src    = (const int*)  d_in[1];
    const int*   dst    = (const int*)  d_in[2];
    const float* basew  = (const float*)d_in[3];
    const float* enc_w1 = (const float*)d_in[4];
    const float* enc_b1 = (const float*)d_in[5];
    const float* enc_w2 = (const float*)d_in[6];
    const float* enc_b2 = (const float*)d_in[7];
    const float* gw1    = (const float*)d_in[8];
    const float* gb1    = (const float*)d_in[9];
    const float* gw2    = (const float*)d_in[10];
    const float* gb2    = (const float*)d_in[11];
    const float* uw1    = (const float*)d_in[12];
    const float* ub1    = (const float*)d_in[13];
    const float* uw2    = (const float*)d_in[14];
    const float* ub2    = (const float*)d_in[15];
    const float* lng    = (const float*)d_in[16];
    const float* lnb    = (const float*)d_in[17];
    const float* rho    = (const float*)d_in[18];
    const float* tw     = (const float*)d_in[19];
    const float* tb     = (const float*)d_in[20];
    float* out = (float*)d_out;

    int nblocks = (NN + NB - 1) / NB;
    k_encoder<<<nblocks, 256>>>(x, enc_w1, enc_b1, enc_w2, enc_b2, gw1, gb1);
    k_rho<<<(NN + 255) / 256, 256>>>(rho);

    for (int l = 0; l < LL; l++) {
        k_edge<<<EE / 32, 256>>>(src, dst, basew, gw2, gb2);
        k_update<<<nblocks, 256>>>(uw1 + l * HH * HH, ub1 + l * HH,
                                   uw2 + l * HH * HH, ub2 + l * HH,
                                   lng + l * HH, lnb + l * HH,
                                   gw1, gb1, l < LL - 1 ? 1 : 0);
    }

    k_head<<<NN / 8, 256>>>(tw, tb, out);
}

// round 8
// speedup vs baseline: 7.3674x; 1.1929x over previous
#include <cuda_runtime.h>
#include <math.h>

#define NN 50000
#define CC 256
#define EE 800000
#define HH 64
#define KK 32
#define LL 2
#define NB 64   // nodes per block in tiled node kernels

// ---- scratch (no allocation allowed) ----
__device__ float g_h[NN * HH];     // node state
__device__ float g_m[NN * HH];     // scatter accumulator (zero-invariant between replays)
__device__ float g_deg[NN];        // weighted degree (zero-invariant between replays)
__device__ float g_rho[NN];        // sigmoid(rho_raw)
__device__ float g_a[NN * HH];     // per-node src-side gate projection: h @ W1[0:64]
__device__ float g_b[NN * HH];     // per-node dst-side gate projection: h @ W1[64:128] + b1
__device__ float g_w0[EE];         // base_w * rho[src] * rho[dst]  (layer-invariant)

// 4x4 outer-product FMA tile: acc[n*4+c] += av.n * wv.c
__device__ __forceinline__ void mm16(const float4 av, const float4 wv, float* acc) {
    acc[0]  = fmaf(av.x, wv.x, acc[0]);  acc[1]  = fmaf(av.x, wv.y, acc[1]);
    acc[2]  = fmaf(av.x, wv.z, acc[2]);  acc[3]  = fmaf(av.x, wv.w, acc[3]);
    acc[4]  = fmaf(av.y, wv.x, acc[4]);  acc[5]  = fmaf(av.y, wv.y, acc[5]);
    acc[6]  = fmaf(av.y, wv.z, acc[6]);  acc[7]  = fmaf(av.y, wv.w, acc[7]);
    acc[8]  = fmaf(av.z, wv.x, acc[8]);  acc[9]  = fmaf(av.z, wv.y, acc[9]);
    acc[10] = fmaf(av.z, wv.z, acc[10]); acc[11] = fmaf(av.z, wv.w, acc[11]);
    acc[12] = fmaf(av.w, wv.x, acc[12]); acc[13] = fmaf(av.w, wv.y, acc[13]);
    acc[14] = fmaf(av.w, wv.z, acc[14]); acc[15] = fmaf(av.w, wv.w, acc[15]);
}

__device__ __forceinline__ void zero16(float* acc) {
#pragma unroll
    for (int k = 0; k < 16; k++) acc[k] = 0.f;
}

__device__ __forceinline__ void red_v4(float* addr, float4 v) {
    asm volatile("red.global.add.v4.f32 [%0], {%1, %2, %3, %4};"
                 :: "l"(addr), "f"(v.x), "f"(v.y), "f"(v.z), "f"(v.w) : "memory");
}

// stage a 64x64 row-major global matrix into sW[64][68]
#define STAGE_W(sW, gptr) do {                                            \
    _Pragma("unroll")                                                     \
    for (int _q = 0; _q < 4; _q++) {                                      \
        int _lin = _q * 256 + tid;                                        \
        *(float4*)&sW[_lin >> 4][(_lin & 15) * 4] =                       \
            *(const float4*)&(gptr)[_lin * 4];                            \
    }                                                                     \
} while (0)

// tiled matvec: acc[16] += sA(64 x nodes) x sW(64 x ch) tile at (ng, cg)
#define MATVEC(sA, sW, acc) do {                                          \
    _Pragma("unroll 8")                                                   \
    for (int _i = 0; _i < 64; _i++) {                                     \
        float4 _av = *(float4*)&sA[_i][ng * 4];                           \
        float4 _wv = *(float4*)&sW[_i][cg * 4];                           \
        mm16(_av, _wv, acc);                                              \
    }                                                                     \
} while (0)

// =====================================================================
// Encoder (tiled): h = relu(relu(x @ W1 + b1) @ W2 + b2), then fused
// gate pre-projections a = h@gW1[0:64], b = h@gW1[64:128]+gb1.
// block = 256 threads = 16 node-groups x 16 channel-groups, 64 nodes/block
// =====================================================================
__global__ void __launch_bounds__(256) k_encoder(
        const float* __restrict__ x,
        const float* __restrict__ w1, const float* __restrict__ b1,
        const float* __restrict__ w2, const float* __restrict__ b2,
        const float* __restrict__ gw1, const float* __restrict__ gb1) {
    __shared__ float sA[64][NB + 4];
    __shared__ float sW[64][68];
    int tid = threadIdx.x;
    int cg = tid & 15, ng = tid >> 4;
    int n0 = blockIdx.x * NB;

    float acc[16];
    zero16(acc);

    // ---- layer1: K=256 in 4 chunks of 64 ----
    for (int kb = 0; kb < 4; kb++) {
#pragma unroll
        for (int q = 0; q < 4; q++) {
            int lin = q * 256 + tid;
            int node = lin >> 4;
            int c4 = (lin & 15) * 4;
            int n = n0 + node;
            float4 v = make_float4(0.f, 0.f, 0.f, 0.f);
            if (n < NN) v = *(const float4*)&x[(size_t)n * CC + kb * 64 + c4];
            sA[c4 + 0][node] = v.x; sA[c4 + 1][node] = v.y;
            sA[c4 + 2][node] = v.z; sA[c4 + 3][node] = v.w;
        }
        STAGE_W(sW, w1 + (size_t)kb * 64 * HH);
        __syncthreads();
        MATVEC(sA, sW, acc);
        __syncthreads();
    }

    // h1 = relu(acc + b1); write transposed into sA, stage w2
    {
        float4 bv = *(const float4*)&b1[cg * 4];
        float bb[4] = {bv.x, bv.y, bv.z, bv.w};
#pragma unroll
        for (int n = 0; n < 4; n++)
#pragma unroll
            for (int c = 0; c < 4; c++)
                sA[cg * 4 + c][ng * 4 + n] = fmaxf(acc[n * 4 + c] + bb[c], 0.f);
    }
    STAGE_W(sW, w2);
    __syncthreads();

    zero16(acc);
    MATVEC(sA, sW, acc);
    __syncthreads();

    // h = relu(acc + b2); store, write transposed into sA
    float hval[16];
    {
        float4 bv = *(const float4*)&b2[cg * 4];
        float bb[4] = {bv.x, bv.y, bv.z, bv.w};
#pragma unroll
        for (int n = 0; n < 4; n++) {
            int node = n0 + ng * 4 + n;
#pragma unroll
            for (int c = 0; c < 4; c++) {
                hval[n * 4 + c] = fmaxf(acc[n * 4 + c] + bb[c], 0.f);
                sA[cg * 4 + c][ng * 4 + n] = hval[n * 4 + c];
            }
            if (node < NN)
                *(float4*)&g_h[(size_t)node * HH + cg * 4] =
                    make_float4(hval[n*4], hval[n*4+1], hval[n*4+2], hval[n*4+3]);
        }
    }
    STAGE_W(sW, gw1);                 // first 64 rows of gate W1
    __syncthreads();

    zero16(acc);
    MATVEC(sA, sW, acc);
#pragma unroll
    for (int n = 0; n < 4; n++) {
        int node = n0 + ng * 4 + n;
        if (node < NN)
            *(float4*)&g_a[(size_t)node * HH + cg * 4] =
                make_float4(acc[n*4], acc[n*4+1], acc[n*4+2], acc[n*4+3]);
    }
    __syncthreads();
    STAGE_W(sW, gw1 + (size_t)64 * HH);  // second 64 rows
    __syncthreads();

    zero16(acc);
    MATVEC(sA, sW, acc);
    {
        float4 bv = *(const float4*)&gb1[cg * 4];
        float bb[4] = {bv.x, bv.y, bv.z, bv.w};
#pragma unroll
        for (int n = 0; n < 4; n++) {
            int node = n0 + ng * 4 + n;
            if (node < NN)
                *(float4*)&g_b[(size_t)node * HH + cg * 4] =
                    make_float4(acc[n*4] + bb[0], acc[n*4+1] + bb[1],
                                acc[n*4+2] + bb[2], acc[n*4+3] + bb[3]);
        }
    }
}

// =====================================================================
// rho = sigmoid(rho_raw)
// =====================================================================
__global__ void k_rho(const float* __restrict__ rho_raw) {
    int i = blockIdx.x * blockDim.x + threadIdx.x;
    if (i < NN) g_rho[i] = 1.f / (1.f + __expf(-rho_raw[i]));
}

// =====================================================================
// w0[e] = base_w[e] * rho[src] * rho[dst]   (layer-invariant edge weight)
// =====================================================================
__global__ void k_w0(const int* __restrict__ src, const int* __restrict__ dst,
                     const float* __restrict__ basew) {
    int i = blockIdx.x * blockDim.x + threadIdx.x;
    if (i < EE)
        g_w0[i] = basew[i] * g_rho[src[i]] * g_rho[dst[i]];
}

// =====================================================================
// Edge kernel: half-warp per edge; lane owns 4 channels (4*sl..4*sl+3).
// Lanes 0-15 handle edge A, 16-31 edge B of each warp instruction.
//   z = relu(a[src] + b[dst]); gate = sigmoid(z @ w2 + b2)
//   wt = w0[e] * gate
//   red.v4: m[dst] += wt*h_src ; deg[dst] += wt
// Warp covers 4 edges in 2 iterations. grid = EE/32 exactly.
// =====================================================================
__global__ void __launch_bounds__(256) k_edge(
        const int* __restrict__ src, const int* __restrict__ dst,
        const float* __restrict__ gw2, const float* __restrict__ gb2) {
    __shared__ float4 sw2[16];
    __shared__ float sb2;
    int tid = threadIdx.x;
    if (tid < 16) sw2[tid] = *(const float4*)&gw2[tid * 4];
    if (tid == 0) sb2 = gb2[0];
    __syncthreads();

    int lane = tid & 31;
    int warp = tid >> 5;
    int sub = lane >> 4;       // which half-warp
    int sl  = lane & 15;       // lane within half
    int e0 = (blockIdx.x * 8 + warp) * 4;

    int4 s4 = *(const int4*)&src[e0];
    int4 d4 = *(const int4*)&dst[e0];
    float4 w04 = *(const float4*)&g_w0[e0];
    int sE[4] = {s4.x, s4.y, s4.z, s4.w};
    int dE[4] = {d4.x, d4.y, d4.z, d4.w};
    float w0E[4] = {w04.x, w04.y, w04.z, w04.w};

    float4 w2v = sw2[sl];
    float b2v = sb2;

    // gather for both iterations up front (MLP)
    int sI[2], dI[2];
    float4 av[2], bv[2], hv[2];
    float w0I[2];
#pragma unroll
    for (int t = 0; t < 2; t++) {
        int ei = t * 2 + sub;
        sI[t] = sE[ei]; dI[t] = dE[ei]; w0I[t] = w0E[ei];
        av[t] = *(const float4*)&g_a[(size_t)sI[t] * HH + sl * 4];
        bv[t] = *(const float4*)&g_b[(size_t)dI[t] * HH + sl * 4];
        hv[t] = *(const float4*)&g_h[(size_t)sI[t] * HH + sl * 4];
    }

    float part[2];
#pragma unroll
    for (int t = 0; t < 2; t++)
        part[t] = fmaxf(av[t].x + bv[t].x, 0.f) * w2v.x
                + fmaxf(av[t].y + bv[t].y, 0.f) * w2v.y
                + fmaxf(av[t].z + bv[t].z, 0.f) * w2v.z
                + fmaxf(av[t].w + bv[t].w, 0.f) * w2v.w;

#pragma unroll
    for (int off = 8; off; off >>= 1) {
        part[0] += __shfl_xor_sync(0xffffffffu, part[0], off);
        part[1] += __shfl_xor_sync(0xffffffffu, part[1], off);
    }

#pragma unroll
    for (int t = 0; t < 2; t++) {
        float gate = 1.f / (1.f + __expf(-(part[t] + b2v)));
        float wt = w0I[t] * gate;
        float4 mv = make_float4(wt * hv[t].x, wt * hv[t].y,
                                wt * hv[t].z, wt * hv[t].w);
        red_v4(&g_m[(size_t)dI[t] * HH + sl * 4], mv);
        if (sl == 0) atomicAdd(&g_deg[dI[t]], wt);
    }
}

// =====================================================================
// Node update (tiled) + LayerNorm (+ fused gate pre-projection).
// block = 256 threads, 64 nodes/block. Resets g_m/g_deg (replay invariant).
// =====================================================================
__global__ void __launch_bounds__(256) k_update(
        const float* __restrict__ uw1, const float* __restrict__ ub1,
        const float* __restrict__ uw2, const float* __restrict__ ub2,
        const float* __restrict__ lng, const float* __restrict__ lnb,
        const float* __restrict__ gw1, const float* __restrict__ gb1,
        int do_pre) {
    __shared__ float sA[64][NB + 4];
    __shared__ float sW[64][68];
    __shared__ float sInv[NB];
    int tid = threadIdx.x;
    int cg = tid & 15, ng = tid >> 4;
    int n0 = blockIdx.x * NB;

    if (tid < NB) {
        int n = n0 + tid;
        float deg = (n < NN) ? g_deg[n] : 0.f;
        sInv[tid] = 1.f / (deg + 1e-8f);
        if (n < NN) g_deg[n] = 0.f;
    }
    __syncthreads();

    // stage neigh = m*inv transposed; reset g_m; stage uw1
#pragma unroll
    for (int q = 0; q < 4; q++) {
        int lin = q * 256 + tid;
        int node = lin >> 4;
        int c4 = (lin & 15) * 4;
        int n = n0 + node;
        float4 v = make_float4(0.f, 0.f, 0.f, 0.f);
        if (n < NN) {
            v = *(const float4*)&g_m[(size_t)n * HH + c4];
            *(float4*)&g_m[(size_t)n * HH + c4] = make_float4(0.f, 0.f, 0.f, 0.f);
        }
        float inv = sInv[node];
        sA[c4 + 0][node] = v.x * inv; sA[c4 + 1][node] = v.y * inv;
        sA[c4 + 2][node] = v.z * inv; sA[c4 + 3][node] = v.w * inv;
    }
    STAGE_W(sW, uw1);
    __syncthreads();

    float acc[16];
    zero16(acc);
    MATVEC(sA, sW, acc);
    __syncthreads();

    // t = relu(acc + ub1) -> transposed into sA; stage uw2
    {
        float4 bv = *(const float4*)&ub1[cg * 4];
        float bb[4] = {bv.x, bv.y, bv.z, bv.w};
#pragma unroll
        for (int n = 0; n < 4; n++)
#pragma unroll
            for (int c = 0; c < 4; c++)
                sA[cg * 4 + c][ng * 4 + n] = fmaxf(acc[n * 4 + c] + bb[c], 0.f);
    }
    STAGE_W(sW, uw2);
    __syncthreads();

    zero16(acc);
    MATVEC(sA, sW, acc);

    // pre = h + u; LayerNorm per node (reduce over 16 cg-threads)
    float pre[16];
    {
        float4 bv = *(const float4*)&ub2[cg * 4];
        float bb[4] = {bv.x, bv.y, bv.z, bv.w};
#pragma unroll
        for (int n = 0; n < 4; n++) {
            int node = n0 + ng * 4 + n;
            float4 h4 = make_float4(0.f, 0.f, 0.f, 0.f);
            if (node < NN) h4 = *(const float4*)&g_h[(size_t)node * HH + cg * 4];
            pre[n * 4 + 0] = h4.x + acc[n * 4 + 0] + bb[0];
            pre[n * 4 + 1] = h4.y + acc[n * 4 + 1] + bb[1];
            pre[n * 4 + 2] = h4.z + acc[n * 4 + 2] + bb[2];
            pre[n * 4 + 3] = h4.w + acc[n * 4 + 3] + bb[3];
        }
    }
    float4 gv = *(const float4*)&lng[cg * 4];
    float4 bv = *(const float4*)&lnb[cg * 4];
    float hn[16];
#pragma unroll
    for (int n = 0; n < 4; n++) {
        float s1 = pre[n*4] + pre[n*4+1] + pre[n*4+2] + pre[n*4+3];
        float s2 = pre[n*4]*pre[n*4] + pre[n*4+1]*pre[n*4+1]
                 + pre[n*4+2]*pre[n*4+2] + pre[n*4+3]*pre[n*4+3];
#pragma unroll
        for (int m = 1; m < 16; m <<= 1) {
            s1 += __shfl_xor_sync(0xffffffffu, s1, m);
            s2 += __shfl_xor_sync(0xffffffffu, s2, m);
        }
        float mean = s1 * (1.f / HH);
        float var  = s2 * (1.f / HH) - mean * mean;
        float inv  = rsqrtf(var + 1e-5f);
        hn[n*4+0] = (pre[n*4+0] - mean) * inv * gv.x + bv.x;
        hn[n*4+1] = (pre[n*4+1] - mean) * inv * gv.y + bv.y;
        hn[n*4+2] = (pre[n*4+2] - mean) * inv * gv.z + bv.z;
        hn[n*4+3] = (pre[n*4+3] - mean) * inv * gv.w + bv.w;
        int node = n0 + ng * 4 + n;
        if (node < NN)
            *(float4*)&g_h[(size_t)node * HH + cg * 4] =
                make_float4(hn[n*4], hn[n*4+1], hn[n*4+2], hn[n*4+3]);
    }

    if (do_pre) {
        __syncthreads();   // all reads of sA/sW done
#pragma unroll
        for (int n = 0; n < 4; n++)
#pragma unroll
            for (int c = 0; c < 4; c++)
                sA[cg * 4 + c][ng * 4 + n] = hn[n * 4 + c];
        STAGE_W(sW, gw1);
        __syncthreads();

        zero16(acc);
        MATVEC(sA, sW, acc);
#pragma unroll
        for (int n = 0; n < 4; n++) {
            int node = n0 + ng * 4 + n;
            if (node < NN)
                *(float4*)&g_a[(size_t)node * HH + cg * 4] =
                    make_float4(acc[n*4], acc[n*4+1], acc[n*4+2], acc[n*4+3]);
        }
        __syncthreads();
        STAGE_W(sW, gw1 + (size_t)64 * HH);
        __syncthreads();

        zero16(acc);
        MATVEC(sA, sW, acc);
        float4 gbv = *(const float4*)&gb1[cg * 4];
        float gb[4] = {gbv.x, gbv.y, gbv.z, gbv.w};
#pragma unroll
        for (int n = 0; n < 4; n++) {
            int node = n0 + ng * 4 + n;
            if (node < NN)
                *(float4*)&g_b[(size_t)node * HH + cg * 4] =
                    make_float4(acc[n*4] + gb[0], acc[n*4+1] + gb[1],
                                acc[n*4+2] + gb[2], acc[n*4+3] + gb[3]);
        }
    }
}

// =====================================================================
// Head: U = softplus(h @ toU_w + toU_b). block = 256 = 8 nodes x 32.
// =====================================================================
__global__ void k_head(const float* __restrict__ tw, const float* __restrict__ tb,
                       float* __restrict__ out) {
    __shared__ float sh[8][HH];
    int tid = threadIdx.x;
    int g = tid >> 5;
    int k = tid & 31;
    int nbase = blockIdx.x * 8;

    for (int idx = tid; idx < 8 * HH; idx += 256) {
        int gg = idx >> 6, jj = idx & 63;
        sh[gg][jj] = g_h[(size_t)(nbase + gg) * HH + jj];
    }
    __syncthreads();

    float a = tb[k];
#pragma unroll
    for (int j = 0; j < HH; j++)
        a = fmaf(sh[g][j], tw[j * KK + k], a);
    out[(size_t)(nbase + g) * KK + k] = log1pf(__expf(-fabsf(a))) + fmaxf(a, 0.f);
}

// =====================================================================
extern "C" void kernel_launch(void* const* d_in, const int* in_sizes, int n_in,
                              void* d_out, int out_size) {
    const float* x      = (const float*)d_in[0];
    const int*   src    = (const int*)  d_in[1];
    const int*   dst    = (const int*)  d_in[2];
    const float* basew  = (const float*)d_in[3];
    const float* enc_w1 = (const float*)d_in[4];
    const float* enc_b1 = (const float*)d_in[5];
    const float* enc_w2 = (const float*)d_in[6];
    const float* enc_b2 = (const float*)d_in[7];
    const float* gw1    = (const float*)d_in[8];
    const float* gb1    = (const float*)d_in[9];
    const float* gw2    = (const float*)d_in[10];
    const float* gb2    = (const float*)d_in[11];
    const float* uw1    = (const float*)d_in[12];
    const float* ub1    = (const float*)d_in[13];
    const float* uw2    = (const float*)d_in[14];
    const float* ub2    = (const float*)d_in[15];
    const float* lng    = (const float*)d_in[16];
    const float* lnb    = (const float*)d_in[17];
    const float* rho    = (const float*)d_in[18];
    const float* tw     = (const float*)d_in[19];
    const float* tb     = (const float*)d_in[20];
    float* out = (float*)d_out;

    int nblocks = (NN + NB - 1) / NB;
    k_encoder<<<nblocks, 256>>>(x, enc_w1, enc_b1, enc_w2, enc_b2, gw1, gb1);
    k_rho<<<(NN + 255) / 256, 256>>>(rho);
    k_w0<<<(EE + 255) / 256, 256>>>(src, dst, basew);

    for (int l = 0; l < LL; l++) {
        k_edge<<<EE / 32, 256>>>(src, dst, gw2, gb2);
        k_update<<<nblocks, 256>>>(uw1 + l * HH * HH, ub1 + l * HH,
                                   uw2 + l * HH * HH, ub2 + l * HH,
                                   lng + l * HH, lnb + l * HH,
                                   gw1, gb1, l < LL - 1 ? 1 : 0);
    }

    k_head<<<NN / 8, 256>>>(tw, tb, out);
}

// round 9
// speedup vs baseline: 7.4613x; 1.0127x over previous
#include <cuda_runtime.h>
#include <math.h>

#define NN 50000
#define CC 256
#define EE 800000
#define HH 64
#define KK 32
#define LL 2
#define NB 64   // nodes per block in tiled node kernels

// ---- scratch (no allocation allowed) ----
__device__ float g_ah[NN * 128];   // per node: [0:64) gate-a proj, [64:128) h
__device__ float g_m[NN * HH];     // scatter accumulator (zero-invariant between replays)
__device__ float g_deg[NN];        // weighted degree (zero-invariant between replays)
__device__ float g_rho[NN];        // sigmoid(rho_raw)
__device__ float g_b[NN * HH];     // per-node dst-side gate projection: h @ W1[64:128] + b1
__device__ float g_w0[EE];         // base_w * rho[src] * rho[dst]  (layer-invariant)
__device__ int   g_soff[EE];       // src * 128  (element offset into g_ah)
__device__ int   g_doff[EE];       // dst * 64   (element offset into g_b / g_m)

// 4x4 outer-product FMA tile: acc[n*4+c] += av.n * wv.c
__device__ __forceinline__ void mm16(const float4 av, const float4 wv, float* acc) {
    acc[0]  = fmaf(av.x, wv.x, acc[0]);  acc[1]  = fmaf(av.x, wv.y, acc[1]);
    acc[2]  = fmaf(av.x, wv.z, acc[2]);  acc[3]  = fmaf(av.x, wv.w, acc[3]);
    acc[4]  = fmaf(av.y, wv.x, acc[4]);  acc[5]  = fmaf(av.y, wv.y, acc[5]);
    acc[6]  = fmaf(av.y, wv.z, acc[6]);  acc[7]  = fmaf(av.y, wv.w, acc[7]);
    acc[8]  = fmaf(av.z, wv.x, acc[8]);  acc[9]  = fmaf(av.z, wv.y, acc[9]);
    acc[10] = fmaf(av.z, wv.z, acc[10]); acc[11] = fmaf(av.z, wv.w, acc[11]);
    acc[12] = fmaf(av.w, wv.x, acc[12]); acc[13] = fmaf(av.w, wv.y, acc[13]);
    acc[14] = fmaf(av.w, wv.z, acc[14]); acc[15] = fmaf(av.w, wv.w, acc[15]);
}

__device__ __forceinline__ void zero16(float* acc) {
#pragma unroll
    for (int k = 0; k < 16; k++) acc[k] = 0.f;
}

__device__ __forceinline__ void red_v4(float* addr, float4 v) {
    asm volatile("red.global.add.v4.f32 [%0], {%1, %2, %3, %4};"
                 :: "l"(addr), "f"(v.x), "f"(v.y), "f"(v.z), "f"(v.w) : "memory");
}

// stage a 64x64 row-major global matrix into sW[64][68]
#define STAGE_W(sW, gptr) do {                                            \
    _Pragma("unroll")                                                     \
    for (int _q = 0; _q < 4; _q++) {                                      \
        int _lin = _q * 256 + tid;                                        \
        *(float4*)&sW[_lin >> 4][(_lin & 15) * 4] =                       \
            *(const float4*)&(gptr)[_lin * 4];                            \
    }                                                                     \
} while (0)

// tiled matvec: acc[16] += sA(64 x nodes) x sW(64 x ch) tile at (ng, cg)
#define MATVEC(sA, sW, acc) do {                                          \
    _Pragma("unroll 8")                                                   \
    for (int _i = 0; _i < 64; _i++) {                                     \
        float4 _av = *(float4*)&sA[_i][ng * 4];                           \
        float4 _wv = *(float4*)&sW[_i][cg * 4];                           \
        mm16(_av, _wv, acc);                                              \
    }                                                                     \
} while (0)

// =====================================================================
// Encoder (tiled): h = relu(relu(x @ W1 + b1) @ W2 + b2), then fused
// gate pre-projections a = h@gW1[0:64] -> g_ah[:,0:64],
// h -> g_ah[:,64:128], b = h@gW1[64:128]+gb1 -> g_b.
// =====================================================================
__global__ void __launch_bounds__(256) k_encoder(
        const float* __restrict__ x,
        const float* __restrict__ w1, const float* __restrict__ b1,
        const float* __restrict__ w2, const float* __restrict__ b2,
        const float* __restrict__ gw1, const float* __restrict__ gb1) {
    __shared__ float sA[64][NB + 4];
    __shared__ float sW[64][68];
    int tid = threadIdx.x;
    int cg = tid & 15, ng = tid >> 4;
    int n0 = blockIdx.x * NB;

    float acc[16];
    zero16(acc);

    // ---- layer1: K=256 in 4 chunks of 64 ----
    for (int kb = 0; kb < 4; kb++) {
#pragma unroll
        for (int q = 0; q < 4; q++) {
            int lin = q * 256 + tid;
            int node = lin >> 4;
            int c4 = (lin & 15) * 4;
            int n = n0 + node;
            float4 v = make_float4(0.f, 0.f, 0.f, 0.f);
            if (n < NN) v = *(const float4*)&x[(size_t)n * CC + kb * 64 + c4];
            sA[c4 + 0][node] = v.x; sA[c4 + 1][node] = v.y;
            sA[c4 + 2][node] = v.z; sA[c4 + 3][node] = v.w;
        }
        STAGE_W(sW, w1 + (size_t)kb * 64 * HH);
        __syncthreads();
        MATVEC(sA, sW, acc);
        __syncthreads();
    }

    // h1 = relu(acc + b1); write transposed into sA, stage w2
    {
        float4 bv = *(const float4*)&b1[cg * 4];
        float bb[4] = {bv.x, bv.y, bv.z, bv.w};
#pragma unroll
        for (int n = 0; n < 4; n++)
#pragma unroll
            for (int c = 0; c < 4; c++)
                sA[cg * 4 + c][ng * 4 + n] = fmaxf(acc[n * 4 + c] + bb[c], 0.f);
    }
    STAGE_W(sW, w2);
    __syncthreads();

    zero16(acc);
    MATVEC(sA, sW, acc);
    __syncthreads();

    // h = relu(acc + b2); store to g_ah[:,64:], write transposed into sA
    float hval[16];
    {
        float4 bv = *(const float4*)&b2[cg * 4];
        float bb[4] = {bv.x, bv.y, bv.z, bv.w};
#pragma unroll
        for (int n = 0; n < 4; n++) {
            int node = n0 + ng * 4 + n;
#pragma unroll
            for (int c = 0; c < 4; c++) {
                hval[n * 4 + c] = fmaxf(acc[n * 4 + c] + bb[c], 0.f);
                sA[cg * 4 + c][ng * 4 + n] = hval[n * 4 + c];
            }
            if (node < NN)
                *(float4*)&g_ah[(size_t)node * 128 + 64 + cg * 4] =
                    make_float4(hval[n*4], hval[n*4+1], hval[n*4+2], hval[n*4+3]);
        }
    }
    STAGE_W(sW, gw1);                 // first 64 rows of gate W1
    __syncthreads();

    zero16(acc);
    MATVEC(sA, sW, acc);
#pragma unroll
    for (int n = 0; n < 4; n++) {
        int node = n0 + ng * 4 + n;
        if (node < NN)
            *(float4*)&g_ah[(size_t)node * 128 + cg * 4] =
                make_float4(acc[n*4], acc[n*4+1], acc[n*4+2], acc[n*4+3]);
    }
    __syncthreads();
    STAGE_W(sW, gw1 + (size_t)64 * HH);  // second 64 rows
    __syncthreads();

    zero16(acc);
    MATVEC(sA, sW, acc);
    {
        float4 bv = *(const float4*)&gb1[cg * 4];
        float bb[4] = {bv.x, bv.y, bv.z, bv.w};
#pragma unroll
        for (int n = 0; n < 4; n++) {
            int node = n0 + ng * 4 + n;
            if (node < NN)
                *(float4*)&g_b[(size_t)node * HH + cg * 4] =
                    make_float4(acc[n*4] + bb[0], acc[n*4+1] + bb[1],
                                acc[n*4+2] + bb[2], acc[n*4+3] + bb[3]);
        }
    }
}

// =====================================================================
// rho = sigmoid(rho_raw)
// =====================================================================
__global__ void k_rho(const float* __restrict__ rho_raw) {
    int i = blockIdx.x * blockDim.x + threadIdx.x;
    if (i < NN) g_rho[i] = 1.f / (1.f + __expf(-rho_raw[i]));
}

// =====================================================================
// w0[e] = base_w * rho[src] * rho[dst]; plus precomputed gather offsets
// =====================================================================
__global__ void k_w0(const int* __restrict__ src, const int* __restrict__ dst,
                     const float* __restrict__ basew) {
    int i = blockIdx.x * blockDim.x + threadIdx.x;
    if (i < EE) {
        int s = src[i], d = dst[i];
        g_w0[i] = basew[i] * g_rho[s] * g_rho[d];
        g_soff[i] = s * 128;
        g_doff[i] = d * 64;
    }
}

// =====================================================================
// Edge kernel: half-warp per edge; lane owns 4 channels.
// Uses precomputed offsets (no per-edge index multiplies).
//   z = relu(a[src] + b[dst]); gate = sigmoid(z @ w2 + b2)
//   wt = w0[e] * gate;  red.v4: m[dst] += wt*h_src ; deg[dst] += wt
// grid = EE/32 exactly.
// =====================================================================
__global__ void __launch_bounds__(256) k_edge(
        const float* __restrict__ gw2, const float* __restrict__ gb2) {
    __shared__ float4 sw2[16];
    __shared__ float sb2;
    int tid = threadIdx.x;
    if (tid < 16) sw2[tid] = *(const float4*)&gw2[tid * 4];
    if (tid == 0) sb2 = gb2[0];
    __syncthreads();

    int lane = tid & 31;
    int warp = tid >> 5;
    int sub = lane >> 4;       // which half-warp
    int sl  = lane & 15;       // lane within half
    int e0 = (blockIdx.x * 8 + warp) * 4;

    int4 so4 = *(const int4*)&g_soff[e0];
    int4 do4 = *(const int4*)&g_doff[e0];
    float4 w04 = *(const float4*)&g_w0[e0];
    int soE[4] = {so4.x, so4.y, so4.z, so4.w};
    int doE[4] = {do4.x, do4.y, do4.z, do4.w};
    float w0E[4] = {w04.x, w04.y, w04.z, w04.w};

    float4 w2v = sw2[sl];
    float b2v = sb2;

    int soI[2], doI[2];
    float4 av[2], bv[2], hv[2];
    float w0I[2];
#pragma unroll
    for (int t = 0; t < 2; t++) {
        int ei = t * 2 + sub;
        soI[t] = soE[ei]; doI[t] = doE[ei]; w0I[t] = w0E[ei];
        const float* ahp = g_ah + soI[t] + sl * 4;
        av[t] = *(const float4*)ahp;
        hv[t] = *(const float4*)(ahp + 64);
        bv[t] = *(const float4*)(g_b + doI[t] + sl * 4);
    }

    float part[2];
#pragma unroll
    for (int t = 0; t < 2; t++)
        part[t] = fmaxf(av[t].x + bv[t].x, 0.f) * w2v.x
                + fmaxf(av[t].y + bv[t].y, 0.f) * w2v.y
                + fmaxf(av[t].z + bv[t].z, 0.f) * w2v.z
                + fmaxf(av[t].w + bv[t].w, 0.f) * w2v.w;

#pragma unroll
    for (int off = 8; off; off >>= 1) {
        part[0] += __shfl_xor_sync(0xffffffffu, part[0], off);
        part[1] += __shfl_xor_sync(0xffffffffu, part[1], off);
    }

#pragma unroll
    for (int t = 0; t < 2; t++) {
        float gate = 1.f / (1.f + __expf(-(part[t] + b2v)));
        float wt = w0I[t] * gate;
        float4 mv = make_float4(wt * hv[t].x, wt * hv[t].y,
                                wt * hv[t].z, wt * hv[t].w);
        red_v4(&g_m[doI[t] + sl * 4], mv);
        if (sl == 0) atomicAdd(&g_deg[doI[t] >> 6], wt);
    }
}

// =====================================================================
// Node update (tiled) + LayerNorm + either next-layer gate projections
// (mode=1) or fused output head (mode=0).
// block = 256 threads, 64 nodes/block. Resets g_m/g_deg (replay invariant).
// =====================================================================
__global__ void __launch_bounds__(256) k_update(
        const float* __restrict__ uw1, const float* __restrict__ ub1,
        const float* __restrict__ uw2, const float* __restrict__ ub2,
        const float* __restrict__ lng, const float* __restrict__ lnb,
        const float* __restrict__ gw1, const float* __restrict__ gb1,
        const float* __restrict__ tw, const float* __restrict__ tb,
        float* __restrict__ out, int mode) {
    __shared__ float sA[64][NB + 4];
    __shared__ float sW[64][68];
    __shared__ float sInv[NB];
    int tid = threadIdx.x;
    int cg = tid & 15, ng = tid >> 4;
    int n0 = blockIdx.x * NB;

    if (tid < NB) {
        int n = n0 + tid;
        float deg = (n < NN) ? g_deg[n] : 0.f;
        sInv[tid] = 1.f / (deg + 1e-8f);
        if (n < NN) g_deg[n] = 0.f;
    }
    __syncthreads();

    // stage neigh = m*inv transposed; reset g_m; stage uw1
#pragma unroll
    for (int q = 0; q < 4; q++) {
        int lin = q * 256 + tid;
        int node = lin >> 4;
        int c4 = (lin & 15) * 4;
        int n = n0 + node;
        float4 v = make_float4(0.f, 0.f, 0.f, 0.f);
        if (n < NN) {
            v = *(const float4*)&g_m[(size_t)n * HH + c4];
            *(float4*)&g_m[(size_t)n * HH + c4] = make_float4(0.f, 0.f, 0.f, 0.f);
        }
        float inv = sInv[node];
        sA[c4 + 0][node] = v.x * inv; sA[c4 + 1][node] = v.y * inv;
        sA[c4 + 2][node] = v.z * inv; sA[c4 + 3][node] = v.w * inv;
    }
    STAGE_W(sW, uw1);
    __syncthreads();

    float acc[16];
    zero16(acc);
    MATVEC(sA, sW, acc);
    __syncthreads();

    // t = relu(acc + ub1) -> transposed into sA; stage uw2
    {
        float4 bv = *(const float4*)&ub1[cg * 4];
        float bb[4] = {bv.x, bv.y, bv.z, bv.w};
#pragma unroll
        for (int n = 0; n < 4; n++)
#pragma unroll
            for (int c = 0; c < 4; c++)
                sA[cg * 4 + c][ng * 4 + n] = fmaxf(acc[n * 4 + c] + bb[c], 0.f);
    }
    STAGE_W(sW, uw2);
    __syncthreads();

    zero16(acc);
    MATVEC(sA, sW, acc);

    // pre = h + u; LayerNorm per node (reduce over 16 cg-threads)
    float pre[16];
    {
        float4 bv = *(const float4*)&ub2[cg * 4];
        float bb[4] = {bv.x, bv.y, bv.z, bv.w};
#pragma unroll
        for (int n = 0; n < 4; n++) {
            int node = n0 + ng * 4 + n;
            float4 h4 = make_float4(0.f, 0.f, 0.f, 0.f);
            if (node < NN)
                h4 = *(const float4*)&g_ah[(size_t)node * 128 + 64 + cg * 4];
            pre[n * 4 + 0] = h4.x + acc[n * 4 + 0] + bb[0];
            pre[n * 4 + 1] = h4.y + acc[n * 4 + 1] + bb[1];
            pre[n * 4 + 2] = h4.z + acc[n * 4 + 2] + bb[2];
            pre[n * 4 + 3] = h4.w + acc[n * 4 + 3] + bb[3];
        }
    }
    float4 gv = *(const float4*)&lng[cg * 4];
    float4 bv = *(const float4*)&lnb[cg * 4];
    float hn[16];
#pragma unroll
    for (int n = 0; n < 4; n++) {
        float s1 = pre[n*4] + pre[n*4+1] + pre[n*4+2] + pre[n*4+3];
        float s2 = pre[n*4]*pre[n*4] + pre[n*4+1]*pre[n*4+1]
                 + pre[n*4+2]*pre[n*4+2] + pre[n*4+3]*pre[n*4+3];
#pragma unroll
        for (int m = 1; m < 16; m <<= 1) {
            s1 += __shfl_xor_sync(0xffffffffu, s1, m);
            s2 += __shfl_xor_sync(0xffffffffu, s2, m);
        }
        float mean = s1 * (1.f / HH);
        float var  = s2 * (1.f / HH) - mean * mean;
        float inv  = rsqrtf(var + 1e-5f);
        hn[n*4+0] = (pre[n*4+0] - mean) * inv * gv.x + bv.x;
        hn[n*4+1] = (pre[n*4+1] - mean) * inv * gv.y + bv.y;
        hn[n*4+2] = (pre[n*4+2] - mean) * inv * gv.z + bv.z;
        hn[n*4+3] = (pre[n*4+3] - mean) * inv * gv.w + bv.w;
    }

    if (mode == 1) {
        // write new h; compute next-layer gate projections a/b
#pragma unroll
        for (int n = 0; n < 4; n++) {
            int node = n0 + ng * 4 + n;
            if (node < NN)
                *(float4*)&g_ah[(size_t)node * 128 + 64 + cg * 4] =
                    make_float4(hn[n*4], hn[n*4+1], hn[n*4+2], hn[n*4+3]);
        }
        __syncthreads();   // all reads of sA/sW done
#pragma unroll
        for (int n = 0; n < 4; n++)
#pragma unroll
            for (int c = 0; c < 4; c++)
                sA[cg * 4 + c][ng * 4 + n] = hn[n * 4 + c];
        STAGE_W(sW, gw1);
        __syncthreads();

        zero16(acc);
        MATVEC(sA, sW, acc);
#pragma unroll
        for (int n = 0; n < 4; n++) {
            int node = n0 + ng * 4 + n;
            if (node < NN)
                *(float4*)&g_ah[(size_t)node * 128 + cg * 4] =
                    make_float4(acc[n*4], acc[n*4+1], acc[n*4+2], acc[n*4+3]);
        }
        __syncthreads();
        STAGE_W(sW, gw1 + (size_t)64 * HH);
        __syncthreads();

        zero16(acc);
        MATVEC(sA, sW, acc);
        float4 gbv = *(const float4*)&gb1[cg * 4];
        float gb[4] = {gbv.x, gbv.y, gbv.z, gbv.w};
#pragma unroll
        for (int n = 0; n < 4; n++) {
            int node = n0 + ng * 4 + n;
            if (node < NN)
                *(float4*)&g_b[(size_t)node * HH + cg * 4] =
                    make_float4(acc[n*4] + gb[0], acc[n*4+1] + gb[1],
                                acc[n*4+2] + gb[2], acc[n*4+3] + gb[3]);
        }
    } else {
        // fused head: U = softplus(h @ toU_w + toU_b)
        __syncthreads();   // all reads of sA/sW done
#pragma unroll
        for (int n = 0; n < 4; n++)
#pragma unroll
            for (int c = 0; c < 4; c++)
                sA[cg * 4 + c][ng * 4 + n] = hn[n * 4 + c];
        // stage toU_w (64 x 32) into sW[:, 0:32]
#pragma unroll
        for (int q = 0; q < 2; q++) {
            int lin = q * 256 + tid;
            int row = lin >> 3, c4 = (lin & 7) * 4;
            *(float4*)&sW[row][c4] = *(const float4*)&tw[row * KK + c4];
        }
        __syncthreads();

        int cg2 = tid & 7, ng2 = tid >> 3;   // 8 col-groups x 32 node-groups
        float a8[8];
#pragma unroll
        for (int k = 0; k < 8; k++) a8[k] = 0.f;
#pragma unroll 8
        for (int i = 0; i < 64; i++) {
            float2 a2 = *(float2*)&sA[i][ng2 * 2];
            float4 w4 = *(float4*)&sW[i][cg2 * 4];
            a8[0] = fmaf(a2.x, w4.x, a8[0]); a8[1] = fmaf(a2.x, w4.y, a8[1]);
            a8[2] = fmaf(a2.x, w4.z, a8[2]); a8[3] = fmaf(a2.x, w4.w, a8[3]);
            a8[4] = fmaf(a2.y, w4.x, a8[4]); a8[5] = fmaf(a2.y, w4.y, a8[5]);
            a8[6] = fmaf(a2.y, w4.z, a8[6]); a8[7] = fmaf(a2.y, w4.w, a8[7]);
        }
        float4 tb4 = *(const float4*)&tb[cg2 * 4];
        float tbb[4] = {tb4.x, tb4.y, tb4.z, tb4.w};
#pragma unroll
        for (int n = 0; n < 2; n++) {
            int node = n0 + ng2 * 2 + n;
            if (node < NN) {
                float4 o;
                float v0 = a8[n*4+0] + tbb[0];
                float v1 = a8[n*4+1] + tbb[1];
                float v2 = a8[n*4+2] + tbb[2];
                float v3 = a8[n*4+3] + tbb[3];
                o.x = log1pf(__expf(-fabsf(v0))) + fmaxf(v0, 0.f);
                o.y = log1pf(__expf(-fabsf(v1))) + fmaxf(v1, 0.f);
                o.z = log1pf(__expf(-fabsf(v2))) + fmaxf(v2, 0.f);
                o.w = log1pf(__expf(-fabsf(v3))) + fmaxf(v3, 0.f);
                *(float4*)&out[(size_t)node * KK + cg2 * 4] = o;
            }
        }
    }
}

// =====================================================================
extern "C" void kernel_launch(void* const* d_in, const int* in_sizes, int n_in,
                              void* d_out, int out_size) {
    const float* x      = (const float*)d_in[0];
    const int*   src    = (const int*)  d_in[1];
    const int*   dst    = (const int*)  d_in[2];
    const float* basew  = (const float*)d_in[3];
    const float* enc_w1 = (const float*)d_in[4];
    const float* enc_b1 = (const float*)d_in[5];
    const float* enc_w2 = (const float*)d_in[6];
    const float* enc_b2 = (const float*)d_in[7];
    const float* gw1    = (const float*)d_in[8];
    const float* gb1    = (const float*)d_in[9];
    const float* gw2    = (const float*)d_in[10];
    const float* gb2    = (const float*)d_in[11];
    const float* uw1    = (const float*)d_in[12];
    const float* ub1    = (const float*)d_in[13];
    const float* uw2    = (const float*)d_in[14];
    const float* ub2    = (const float*)d_in[15];
    const float* lng    = (const float*)d_in[16];
    const float* lnb    = (const float*)d_in[17];
    const float* rho    = (const float*)d_in[18];
    const float* tw     = (const float*)d_in[19];
    const float* tb     = (const float*)d_in[20];
    float* out = (float*)d_out;

    int nblocks = (NN + NB - 1) / NB;
    k_encoder<<<nblocks, 256>>>(x, enc_w1, enc_b1, enc_w2, enc_b2, gw1, gb1);
    k_rho<<<(NN + 255) / 256, 256>>>(rho);
    k_w0<<<(EE + 255) / 256, 256>>>(src, dst, basew);

    for (int l = 0; l < LL; l++) {
        k_edge<<<EE / 32, 256>>>(gw2, gb2);
        k_update<<<nblocks, 256>>>(uw1 + l * HH * HH, ub1 + l * HH,
                                   uw2 + l * HH * HH, ub2 + l * HH,
                                   lng + l * HH, lnb + l * HH,
                                   gw1, gb1, tw, tb, out,
                                   l < LL - 1 ? 1 : 0);
    }
}